// round 11
// baseline (speedup 1.0000x reference)
#include <cuda_runtime.h>
#include <cuda_bf16.h>
#include <math.h>
#include <stdint.h>

// ---------------- problem constants (fixed shapes) ----------------
#define N_PTS    160000
#define NL0      100000
#define NL1       60000
#define NG       128
#define NC       128
#define GEMM_ROWS 256
#define GEMM_BLOCKS (N_PTS / GEMM_ROWS)   // 625

// ---------------- device scratch (no allocation allowed) ----------------
__device__ float g_fused[(size_t)N_PTS * NC];           // X @ W (no T4)
__device__ float g_T4[4 * NC];
__device__ __align__(16) __nv_bfloat16 g_Whi[NC * NC];  // [n][k] = bf16(W[k][n])
__device__ __align__(16) __nv_bfloat16 g_Wlo[NC * NC];  // residual
__device__ float g_partial[NC * GEMM_BLOCKS];
__device__ float g_partialsq[NC * GEMM_BLOCKS];
__device__ __align__(16) float g_scale[NC];
__device__ __align__(16) float g_shift[NC];
__device__ float g_kth[NG];

#define CAND_CAP 2048
__device__ float g_cand[(size_t)NG * CAND_CAP];
__device__ int   g_cnt[NG];

#define R2_L0 1.44f
#define R2_L1 2.25f

// ---------------- mma.sync bf16 (baseline PTX, works on sm_103) ------
#define MMA16816(d, a, b) \
    asm volatile("mma.sync.aligned.m16n8k16.row.col.f32.bf16.bf16.f32 " \
        "{%0,%1,%2,%3}, {%4,%5,%6,%7}, {%8,%9}, {%0,%1,%2,%3};" \
        : "+f"((d)[0]), "+f"((d)[1]), "+f"((d)[2]), "+f"((d)[3]) \
        : "r"((a)[0]), "r"((a)[1]), "r"((a)[2]), "r"((a)[3]), \
          "r"((b)[0]), "r"((b)[1]))

// pack two floats to bf16x2 (lo = a, hi = b)
#define CVT_BF16X2(res, a, b) \
    asm("cvt.rn.bf16x2.f32 %0, %1, %2;" : "=r"(res) : "f"(b), "f"(a))

// split (a,b) into bf16 hi pair + bf16 residual pair
__device__ __forceinline__ void split2(float a, float b, uint32_t& hp, uint32_t& lp) {
    CVT_BF16X2(hp, a, b);
    float ha = __uint_as_float(hp << 16);
    float hb = __uint_as_float(hp & 0xffff0000u);
    float ra = a - ha, rb = b - hb;
    CVT_BF16X2(lp, ra, rb);
}

// gemm smem layout: padded rows of 136 bf16 (272 B)
#define APAD 136
#define SM_BHI 0
#define SM_BLO (SM_BHI + 128 * APAD * 2)      // 34816
#define SM_AHI (SM_BLO + 128 * APAD * 2)      // 69632
#define SM_ALO (SM_AHI + 256 * APAD * 2)      // 139264
#define GEMM_SMEM (SM_ALO + 256 * APAD * 2)   // 208896 (~204 KB)

// =====================================================================
// W-prep: g_Whi/g_Wlo[n][k] = bf16 split of W_fuse[k][n], k<128
// =====================================================================
__global__ void wprep_kernel(const float* __restrict__ Wf) {
    int i = blockIdx.x * 256 + threadIdx.x;   // 16384
    int n = i >> 7, k = i & 127;
    float v = Wf[k * 128 + n];
    __nv_bfloat16 h = __float2bfloat16(v);
    float r = v - __bfloat162float(h);
    g_Whi[n * 128 + k] = h;
    g_Wlo[n * 128 + k] = __float2bfloat16(r);
}

// =====================================================================
// T4 = text_feats @ W_fuse[128:256] + b_fuse (exact fp32)
// =====================================================================
__global__ void t4_kernel(const float* __restrict__ text,
                          const float* __restrict__ Wf,
                          const float* __restrict__ bfuse) {
    int t = threadIdx.x >> 7;
    int c = threadIdx.x & 127;
    float acc = bfuse[c];
    #pragma unroll 8
    for (int k = 0; k < 128; k++)
        acc = fmaf(text[t * 128 + k], Wf[(128 + k) * 128 + c], acc);
    g_T4[t * 128 + c] = acc;
}

// =====================================================================
// GEMM: g_fused = X @ W via mma.sync bf16 hi/lo 3-pass.
// 256x128 tile per block, 8 warps (4 row-strips x 2 col-strips),
// warp tile 64x64 = 4 M-tiles x 8 N-tiles of m16n8k16.
// =====================================================================
__global__ void __launch_bounds__(256, 1)
gemm_kernel(const float* __restrict__ bf) {
    extern __shared__ char smem[];
    __nv_bfloat16* sBhi = (__nv_bfloat16*)(smem + SM_BHI);
    __nv_bfloat16* sBlo = (__nv_bfloat16*)(smem + SM_BLO);
    __nv_bfloat16* sAhi = (__nv_bfloat16*)(smem + SM_AHI);
    __nv_bfloat16* sAlo = (__nv_bfloat16*)(smem + SM_ALO);

    const int tid  = threadIdx.x;
    const int warp = tid >> 5;
    const int lane = tid & 31;
    const int g  = lane >> 2;          // 0..7
    const int tg = lane & 3;           // 0..3
    const int brow = blockIdx.x * GEMM_ROWS;

    // ---- load B (W^T hi/lo) into padded smem rows ----
    {
        int n = tid & 127;
        const uint4* src = (const uint4*)((tid < 128 ? g_Whi : g_Wlo) + n * 128);
        __nv_bfloat16* dst = (tid < 128 ? sBhi : sBlo) + n * APAD;
        #pragma unroll
        for (int j = 0; j < 16; j++)           // FIX: full 128 bf16 row = 16 uint4 (was 8)
            *(uint4*)(dst + j * 8) = src[j];
    }

    // ---- load + convert X tile (coalesced) ----
    {
        const float4* bf4 = (const float4*)bf;
        #pragma unroll 4
        for (int it = 0; it < 32; it++) {
            int idx = it * 256 + tid;            // 8192 float4s
            int r = idx >> 5, c4 = idx & 31;
            float4 v = bf4[(size_t)(brow + r) * 32 + c4];
            uint32_t h0, l0, h1, l1;
            split2(v.x, v.y, h0, l0);
            split2(v.z, v.w, h1, l1);
            *(uint2*)(sAhi + r * APAD + c4 * 4) = make_uint2(h0, h1);
            *(uint2*)(sAlo + r * APAD + c4 * 4) = make_uint2(l0, l1);
        }
    }
    __syncthreads();

    const int wm = (warp & 3) * 64;    // row offset in tile
    const int wn = (warp >> 2) * 64;   // col offset

    float acc[4][8][4];
    #pragma unroll
    for (int mt = 0; mt < 4; mt++)
        #pragma unroll
        for (int nt = 0; nt < 8; nt++)
            #pragma unroll
            for (int r = 0; r < 4; r++) acc[mt][nt][r] = 0.f;

    #pragma unroll 1
    for (int pass = 0; pass < 3; pass++) {
        const __nv_bfloat16* A = (pass == 2) ? sAlo : sAhi;
        const __nv_bfloat16* B = (pass == 1) ? sBlo : sBhi;
        const __nv_bfloat16* Ab = A + (wm + g) * APAD + tg * 2;
        const __nv_bfloat16* Bb = B + (wn + g) * APAD + tg * 2;
        #pragma unroll 1
        for (int ks = 0; ks < 8; ks++) {
            const int k0 = ks * 16;
            uint32_t a[4][4], b[8][2];
            #pragma unroll
            for (int mt = 0; mt < 4; mt++) {
                const __nv_bfloat16* p = Ab + mt * (16 * APAD) + k0;
                a[mt][0] = *(const uint32_t*)(p);
                a[mt][1] = *(const uint32_t*)(p + 8 * APAD);
                a[mt][2] = *(const uint32_t*)(p + 8);
                a[mt][3] = *(const uint32_t*)(p + 8 * APAD + 8);
            }
            #pragma unroll
            for (int nt = 0; nt < 8; nt++) {
                const __nv_bfloat16* p = Bb + nt * (8 * APAD) + k0;
                b[nt][0] = *(const uint32_t*)(p);
                b[nt][1] = *(const uint32_t*)(p + 8);
            }
            #pragma unroll
            for (int mt = 0; mt < 4; mt++)
                #pragma unroll
                for (int nt = 0; nt < 8; nt++)
                    MMA16816(acc[mt][nt], a[mt], b[nt]);
        }
    }

    // ---- epilogue: write X@W ----
    #pragma unroll
    for (int mt = 0; mt < 4; mt++) {
        size_t r0 = (size_t)(brow + wm + mt * 16 + g) * 128;
        size_t r1 = r0 + 8 * 128;
        #pragma unroll
        for (int nt = 0; nt < 8; nt++) {
            int c = wn + nt * 8 + tg * 2;
            *(float2*)&g_fused[r0 + c] = make_float2(acc[mt][nt][0], acc[mt][nt][1]);
            *(float2*)&g_fused[r1 + c] = make_float2(acc[mt][nt][2], acc[mt][nt][3]);
        }
    }
}

// =====================================================================
// pstats: per-block channel partials of (fused + T4[bidx])
// =====================================================================
__global__ void __launch_bounds__(256)
pstats_kernel(const int* __restrict__ bidx) {
    __shared__ float sT4[512];
    __shared__ int sB[256];
    __shared__ float rs[256], rq[256];
    const int tid = threadIdx.x;
    const int brow = blockIdx.x * GEMM_ROWS;
    for (int i = tid; i < 512; i += 256) sT4[i] = g_T4[i];
    sB[tid] = bidx[brow + tid];
    __syncthreads();

    const int c = tid & 127, half = tid >> 7;
    float s = 0.f, q = 0.f;
    #pragma unroll 4
    for (int r = half; r < 256; r += 2) {
        float v = g_fused[(size_t)(brow + r) * 128 + c] + sT4[sB[r] * 128 + c];
        s += v; q += v * v;
    }
    rs[tid] = s; rq[tid] = q;
    __syncthreads();
    if (tid < 128) {
        s = rs[tid] + rs[tid + 128];
        q = rq[tid] + rq[tid + 128];
        g_partial[tid * GEMM_BLOCKS + blockIdx.x]   = s;
        g_partialsq[tid * GEMM_BLOCKS + blockIdx.x] = q;
    }
}

// =====================================================================
// stats: reduce partials -> BN scale/shift (deterministic)
// =====================================================================
__global__ void stats_kernel(const float* __restrict__ gamma,
                             const float* __restrict__ beta) {
    const int c = blockIdx.x;
    const int tid = threadIdx.x;
    __shared__ float rs[256], rq[256];
    float s = 0.f, q = 0.f;
    for (int b = tid; b < GEMM_BLOCKS; b += 256) {
        s += g_partial[c * GEMM_BLOCKS + b];
        q += g_partialsq[c * GEMM_BLOCKS + b];
    }
    rs[tid] = s; rq[tid] = q;
    __syncthreads();
    for (int o = 128; o > 0; o >>= 1) {
        if (tid < o) { rs[tid] += rs[tid + o]; rq[tid] += rq[tid + o]; }
        __syncthreads();
    }
    if (tid == 0) {
        float mu  = rs[0] / (float)N_PTS;
        float var = rq[0] / (float)N_PTS - mu * mu;
        float sc  = gamma[c] * rsqrtf(var + 1e-5f);
        g_scale[c] = sc;
        g_shift[c] = beta[c] - mu * sc;
    }
}

// =====================================================================
// head2: x = relu(BN(fused + T4[bidx])); preds
// =====================================================================
__global__ void __launch_bounds__(256)
head2_kernel(const int* __restrict__ bidx,
             const float* __restrict__ Wb, const float* __restrict__ bb,
             const float* __restrict__ Wc, const float* __restrict__ bc,
             float* __restrict__ out) {
    __shared__ float4 sw[9][32];
    __shared__ float4 ssc[32], ssh[32];
    __shared__ float sb[9];
    __shared__ __align__(16) float sT4[512];
    const int tid = threadIdx.x;
    for (int i = tid; i < 288; i += 256) {
        int j = i >> 5, k4 = i & 31, k = k4 * 4;
        float4 w;
        if (j < 7) w = make_float4(Wb[(k+0)*7+j], Wb[(k+1)*7+j], Wb[(k+2)*7+j], Wb[(k+3)*7+j]);
        else { int jc = j - 7;
               w = make_float4(Wc[(k+0)*2+jc], Wc[(k+1)*2+jc], Wc[(k+2)*2+jc], Wc[(k+3)*2+jc]); }
        sw[j][k4] = w;
    }
    for (int i = tid; i < 512; i += 256) sT4[i] = g_T4[i];
    if (tid < 32) { ssc[tid] = ((const float4*)g_scale)[tid]; ssh[tid] = ((const float4*)g_shift)[tid]; }
    if (tid < 9) sb[tid] = (tid < 7) ? bb[tid] : bc[tid - 7];
    __syncthreads();

    const int p = blockIdx.x * 256 + tid;
    const int bofs = bidx[p] * 32;       // float4 index into sT4
    float acc[9];
    #pragma unroll
    for (int j = 0; j < 9; j++) acc[j] = sb[j];
    const float4* gf = (const float4*)g_fused;
    const float4* t4f = (const float4*)sT4;
    #pragma unroll 4
    for (int k4 = 0; k4 < 32; k4++) {
        float4 f = gf[(size_t)p * 32 + k4];
        float4 t = t4f[bofs + k4];
        float4 sc = ssc[k4], sh = ssh[k4];
        float x0 = fmaxf(fmaf(f.x + t.x, sc.x, sh.x), 0.f);
        float x1 = fmaxf(fmaf(f.y + t.y, sc.y, sh.y), 0.f);
        float x2 = fmaxf(fmaf(f.z + t.z, sc.z, sh.z), 0.f);
        float x3 = fmaxf(fmaf(f.w + t.w, sc.w, sh.w), 0.f);
        #pragma unroll
        for (int j = 0; j < 9; j++) {
            float4 w = sw[j][k4];
            acc[j] = fmaf(x0, w.x, acc[j]);
            acc[j] = fmaf(x1, w.y, acc[j]);
            acc[j] = fmaf(x2, w.z, acc[j]);
            acc[j] = fmaf(x3, w.w, acc[j]);
        }
    }
    float* o = out + (size_t)p * 9;
    o[0] = acc[0]; o[1] = acc[1]; o[2] = acc[2];
    o[3] = expf(acc[3]); o[4] = expf(acc[4]); o[5] = expf(acc[5]);
    o[6] = acc[6]; o[7] = acc[7]; o[8] = acc[8];
}

// ===================== assignment path (unchanged) =====================
__global__ void zero_cnt_kernel() { g_cnt[threadIdx.x] = 0; }

__global__ void __launch_bounds__(256)
cand_kernel(const float* __restrict__ p0, const float* __restrict__ p1,
            const float* __restrict__ boxes, const int* __restrict__ labels) {
    __shared__ float4 sc0[NG], sc1[NG];
    const int tid = threadIdx.x;
    if (tid < NG) {
        float cx = boxes[tid * 7 + 0], cy = boxes[tid * 7 + 1], cz = boxes[tid * 7 + 2];
        int lvl = labels[tid];
        sc0[tid] = make_float4(cx, cy, cz, (lvl == 0) ? R2_L0 : -1.0f);
        sc1[tid] = make_float4(cx, cy, cz, (lvl == 1) ? R2_L1 : -1.0f);
    }
    __syncthreads();

    const int p = blockIdx.x * 256 + tid;
    float px, py, pz; const float4* Cc;
    if (p < NL0) { px = p0[3 * p]; py = p0[3 * p + 1]; pz = p0[3 * p + 2]; Cc = sc0; }
    else { int q = p - NL0; px = p1[3 * q]; py = p1[3 * q + 1]; pz = p1[3 * q + 2]; Cc = sc1; }

    #pragma unroll 4
    for (int g = 0; g < NG; g++) {
        float4 c = Cc[g];
        float dx = px - c.x, dy = py - c.y, dz = pz - c.z;
        float d2 = fmaf(dz, dz, fmaf(dy, dy, dx * dx));
        if (d2 < c.w) {
            int idx = atomicAdd(&g_cnt[g], 1);
            if (idx < CAND_CAP) g_cand[(size_t)g * CAND_CAP + idx] = d2;
        }
    }
}

#define NBUCK 4096
#define BSCALE 235.0f
#define BCANDMAX 2048
#define KSEL 33

__global__ void __launch_bounds__(512)
select_kernel(const float* __restrict__ p0, const float* __restrict__ p1,
              const float* __restrict__ boxes, const int* __restrict__ labels) {
    const int g = blockIdx.x;
    const int tid = threadIdx.x;
    __shared__ unsigned hist[NBUCK];
    __shared__ unsigned csum[512];
    __shared__ float bcand[BCANDMAX];
    __shared__ int sInfo[3];

    const int lvl = labels[g];
    const float* pts = lvl ? p1 : p0;
    const int n = lvl ? NL1 : NL0;
    const float cx = boxes[g * 7 + 0], cy = boxes[g * 7 + 1], cz = boxes[g * 7 + 2];

    const int cnt = g_cnt[g];
    const bool ok = (cnt >= KSEL && cnt <= CAND_CAP);
    const float* src = &g_cand[(size_t)g * CAND_CAP];
    const int m = ok ? cnt : n;

    for (int i = tid; i < NBUCK; i += 512) hist[i] = 0u;
    if (tid == 0) sInfo[2] = 0;
    __syncthreads();

    for (int i = tid; i < m; i += 512) {
        float d2;
        if (ok) d2 = src[i];
        else {
            float dx = pts[3 * i] - cx, dy = pts[3 * i + 1] - cy, dz = pts[3 * i + 2] - cz;
            d2 = fmaf(dz, dz, fmaf(dy, dy, dx * dx));
        }
        int b = (int)(sqrtf(d2) * BSCALE); b = b > (NBUCK - 1) ? (NBUCK - 1) : b;
        atomicAdd(&hist[b], 1u);
    }
    __syncthreads();

    unsigned cs = 0;
    #pragma unroll
    for (int i = 0; i < 8; i++) cs += hist[tid * 8 + i];
    csum[tid] = cs;
    __syncthreads();
    if (tid == 0) {
        unsigned run = 0; int chunk = 0;
        while (chunk < 512 && run + csum[chunk] < KSEL) { run += csum[chunk]; chunk++; }
        int B = chunk * 8;
        while (run + hist[B] < KSEL) { run += hist[B]; B++; }
        sInfo[0] = B; sInfo[1] = (int)run;
    }
    __syncthreads();
    const int B = sInfo[0];

    for (int i = tid; i < m; i += 512) {
        float d2;
        if (ok) d2 = src[i];
        else {
            float dx = pts[3 * i] - cx, dy = pts[3 * i + 1] - cy, dz = pts[3 * i + 2] - cz;
            d2 = fmaf(dz, dz, fmaf(dy, dy, dx * dx));
        }
        int b = (int)(sqrtf(d2) * BSCALE); b = b > (NBUCK - 1) ? (NBUCK - 1) : b;
        if (b == B) {
            int pos = atomicAdd(&sInfo[2], 1);
            if (pos < BCANDMAX) bcand[pos] = d2;
        }
    }
    __syncthreads();
    if (tid == 0) {
        int mb = sInfo[2]; if (mb > BCANDMAX) mb = BCANDMAX;
        int need = KSEL - sInfo[1];
        float kth = 1e8f;
        for (int r = 0; r < need; r++) {
            float best = 3.4e38f; int bi = 0;
            for (int i = 0; i < mb; i++) { float v = bcand[i]; if (v < best) { best = v; bi = i; } }
            kth = best; bcand[bi] = 3.4e38f;
        }
        g_kth[g] = kth;
    }
}

__global__ void __launch_bounds__(256)
assign_kernel(const float* __restrict__ p0, const float* __restrict__ p1,
              const float* __restrict__ boxes, const int* __restrict__ labels,
              float* __restrict__ out) {
    __shared__ float4 sc0[NG], sc1[NG];
    const int tid = threadIdx.x;
    if (tid < NG) {
        float cx = boxes[tid * 7 + 0], cy = boxes[tid * 7 + 1], cz = boxes[tid * 7 + 2];
        int lvl = labels[tid];
        float kth = g_kth[tid];
        sc0[tid] = make_float4(cx, cy, cz, (lvl == 0) ? kth : -1.0f);
        sc1[tid] = make_float4(cx, cy, cz, (lvl == 1) ? kth : -1.0f);
    }
    __syncthreads();

    const int p = blockIdx.x * 256 + tid;
    float px, py, pz; const float4* Cc;
    if (p < NL0) { px = p0[3 * p]; py = p0[3 * p + 1]; pz = p0[3 * p + 2]; Cc = sc0; }
    else { int q = p - NL0; px = p1[3 * q]; py = p1[3 * q + 1]; pz = p1[3 * q + 2]; Cc = sc1; }

    float best = 3.4e38f; int bi = 0;
    float gbest = 1e8f;   int gi = -1;
    #pragma unroll 4
    for (int g = 0; g < NG; g++) {
        float4 c = Cc[g];
        float dx = px - c.x, dy = py - c.y, dz = pz - c.z;
        float d2 = fmaf(dz, dz, fmaf(dy, dy, dx * dx));
        if (d2 < best) { best = d2; bi = g; }
        if (d2 < c.w && d2 < gbest) { gbest = d2; gi = g; }
    }
    int a = (gi == bi) ? gi : -1;
    out[(size_t)N_PTS * 9 + p] = (float)a;
}

// =====================================================================
// launch
// =====================================================================
extern "C" void kernel_launch(void* const* d_in, const int* in_sizes, int n_in,
                              void* d_out, int out_size) {
    const float* bf    = (const float*)d_in[0];
    const float* text  = (const float*)d_in[1];
    const float* Wf    = (const float*)d_in[2];
    const float* bfu   = (const float*)d_in[3];
    const float* gamma = (const float*)d_in[4];
    const float* beta  = (const float*)d_in[5];
    const float* Wb    = (const float*)d_in[6];
    const float* bb    = (const float*)d_in[7];
    const float* Wc    = (const float*)d_in[8];
    const float* bc    = (const float*)d_in[9];
    const float* p0    = (const float*)d_in[10];
    const float* p1    = (const float*)d_in[11];
    const bool sig = (in_sizes[12] == 128 * 7);
    const float* boxes  = (const float*)d_in[sig ? 12 : 14];
    const int*   bidx   = (const int*)  d_in[sig ? 13 : 12];
    const int*   labels = (const int*)  d_in[sig ? 14 : 13];
    float* out = (float*)d_out;

    cudaFuncSetAttribute(gemm_kernel, cudaFuncAttributeMaxDynamicSharedMemorySize,
                         GEMM_SMEM);

    // assignment path
    zero_cnt_kernel<<<1, NG>>>();
    cand_kernel<<<N_PTS / 256, 256>>>(p0, p1, boxes, labels);
    select_kernel<<<NG, 512>>>(p0, p1, boxes, labels);
    assign_kernel<<<N_PTS / 256, 256>>>(p0, p1, boxes, labels, out);

    // head path
    wprep_kernel<<<64, 256>>>(Wf);
    t4_kernel<<<1, 512>>>(text, Wf, bfu);
    gemm_kernel<<<GEMM_BLOCKS, 256, GEMM_SMEM>>>(bf);
    pstats_kernel<<<GEMM_BLOCKS, 256>>>(bidx);
    stats_kernel<<<128, 256>>>(gamma, beta);
    head2_kernel<<<N_PTS / 256, 256>>>(bidx, Wb, bb, Wc, bc, out);
}

// round 13
// speedup vs baseline: 1.4477x; 1.4477x over previous
#include <cuda_runtime.h>
#include <cuda_bf16.h>
#include <math.h>
#include <stdint.h>

// ---------------- problem constants (fixed shapes) ----------------
#define N_PTS    160000
#define NL0      100000
#define NL1       60000
#define NG       128
#define NC       128
#define GEMM_ROWS 256
#define GEMM_BLOCKS (N_PTS / GEMM_ROWS)   // 625

// ---------------- device scratch (no allocation allowed) ----------------
__device__ float g_fused[(size_t)N_PTS * NC];           // X @ W (no T4)
__device__ float g_T4[4 * NC];
__device__ __align__(16) __nv_bfloat16 g_Whi[NC * NC];  // [n][k] = bf16(W[k][n])
__device__ __align__(16) __nv_bfloat16 g_Wlo[NC * NC];  // residual
__device__ float g_partial[NC * GEMM_BLOCKS];
__device__ float g_partialsq[NC * GEMM_BLOCKS];
__device__ __align__(16) float g_scale[NC];
__device__ __align__(16) float g_shift[NC];
__device__ float g_kth[NG];

#define CAND_CAP 2048
__device__ float g_cand[(size_t)NG * CAND_CAP];
__device__ int   g_cnt[NG];

#define R2_L0 1.44f
#define R2_L1 2.25f

// ---------------- mma.sync bf16 (baseline PTX, works on sm_103) ------
#define MMA16816(d, a, b) \
    asm volatile("mma.sync.aligned.m16n8k16.row.col.f32.bf16.bf16.f32 " \
        "{%0,%1,%2,%3}, {%4,%5,%6,%7}, {%8,%9}, {%0,%1,%2,%3};" \
        : "+f"((d)[0]), "+f"((d)[1]), "+f"((d)[2]), "+f"((d)[3]) \
        : "r"((a)[0]), "r"((a)[1]), "r"((a)[2]), "r"((a)[3]), \
          "r"((b)[0]), "r"((b)[1]))

// pack two floats to bf16x2 (lo = a, hi = b)
#define CVT_BF16X2(res, a, b) \
    asm("cvt.rn.bf16x2.f32 %0, %1, %2;" : "=r"(res) : "f"(b), "f"(a))

// split (a,b) into bf16 hi pair + bf16 residual pair
__device__ __forceinline__ void split2(float a, float b, uint32_t& hp, uint32_t& lp) {
    CVT_BF16X2(hp, a, b);
    float ha = __uint_as_float(hp << 16);
    float hb = __uint_as_float(hp & 0xffff0000u);
    float ra = a - ha, rb = b - hb;
    CVT_BF16X2(lp, ra, rb);
}

// gemm smem layout: padded rows of 136 bf16 (272 B)
#define APAD 136
#define SM_BHI 0
#define SM_BLO (SM_BHI + 128 * APAD * 2)      // 34816
#define SM_AHI (SM_BLO + 128 * APAD * 2)      // 69632
#define SM_ALO (SM_AHI + 256 * APAD * 2)      // 139264
#define GEMM_SMEM (SM_ALO + 256 * APAD * 2)   // 208896 (~204 KB)

// =====================================================================
// W-prep: g_Whi/g_Wlo[n][k] = bf16 split of W_fuse[k][n], k<128
// =====================================================================
__global__ void wprep_kernel(const float* __restrict__ Wf) {
    int i = blockIdx.x * 256 + threadIdx.x;   // 16384
    int n = i >> 7, k = i & 127;
    float v = Wf[k * 128 + n];
    __nv_bfloat16 h = __float2bfloat16(v);
    float r = v - __bfloat162float(h);
    g_Whi[n * 128 + k] = h;
    g_Wlo[n * 128 + k] = __float2bfloat16(r);
}

// =====================================================================
// T4 = text_feats @ W_fuse[128:256] + b_fuse (exact fp32)
// =====================================================================
__global__ void t4_kernel(const float* __restrict__ text,
                          const float* __restrict__ Wf,
                          const float* __restrict__ bfuse) {
    int t = threadIdx.x >> 7;
    int c = threadIdx.x & 127;
    float acc = bfuse[c];
    #pragma unroll 8
    for (int k = 0; k < 128; k++)
        acc = fmaf(text[t * 128 + k], Wf[(128 + k) * 128 + c], acc);
    g_T4[t * 128 + c] = acc;
}

// =====================================================================
// GEMM: g_fused = X @ W via mma.sync bf16 hi/lo 3-pass.
// 256x128 tile per block, 16 warps (8 row-strips x 2 col-strips),
// warp tile 32x64 = 2 M-tiles x 8 N-tiles of m16n8k16.
// 512 threads: 4 warps/SMSP to overlap LDS->MMA dependency chains.
// =====================================================================
__global__ void __launch_bounds__(512, 1)
gemm_kernel(const float* __restrict__ bf) {
    extern __shared__ char smem[];
    __nv_bfloat16* sBhi = (__nv_bfloat16*)(smem + SM_BHI);
    __nv_bfloat16* sBlo = (__nv_bfloat16*)(smem + SM_BLO);
    __nv_bfloat16* sAhi = (__nv_bfloat16*)(smem + SM_AHI);
    __nv_bfloat16* sAlo = (__nv_bfloat16*)(smem + SM_ALO);

    const int tid  = threadIdx.x;
    const int warp = tid >> 5;
    const int lane = tid & 31;
    const int g  = lane >> 2;          // 0..7
    const int tg = lane & 3;           // 0..3
    const int brow = blockIdx.x * GEMM_ROWS;

    // ---- load B (W^T hi/lo) into padded smem rows (threads 0..255) ----
    if (tid < 256) {
        int n = tid & 127;
        const uint4* src = (const uint4*)((tid < 128 ? g_Whi : g_Wlo) + n * 128);
        __nv_bfloat16* dst = (tid < 128 ? sBhi : sBlo) + n * APAD;
        #pragma unroll
        for (int j = 0; j < 16; j++)
            *(uint4*)(dst + j * 8) = src[j];
    }

    // ---- load + convert X tile (coalesced, all 512 threads) ----
    {
        const float4* bf4 = (const float4*)bf;
        #pragma unroll 4
        for (int it = 0; it < 16; it++) {
            int idx = it * 512 + tid;            // 8192 float4s
            int r = idx >> 5, c4 = idx & 31;
            float4 v = bf4[(size_t)(brow + r) * 32 + c4];
            uint32_t h0, l0, h1, l1;
            split2(v.x, v.y, h0, l0);
            split2(v.z, v.w, h1, l1);
            *(uint2*)(sAhi + r * APAD + c4 * 4) = make_uint2(h0, h1);
            *(uint2*)(sAlo + r * APAD + c4 * 4) = make_uint2(l0, l1);
        }
    }
    __syncthreads();

    const int wm = (warp & 7) * 32;    // row offset in tile (8 strips)
    const int wn = (warp >> 3) * 64;   // col offset (2 strips)

    float acc[2][8][4];
    #pragma unroll
    for (int mt = 0; mt < 2; mt++)
        #pragma unroll
        for (int nt = 0; nt < 8; nt++)
            #pragma unroll
            for (int r = 0; r < 4; r++) acc[mt][nt][r] = 0.f;

    #pragma unroll 1
    for (int pass = 0; pass < 3; pass++) {
        const __nv_bfloat16* A = (pass == 2) ? sAlo : sAhi;
        const __nv_bfloat16* B = (pass == 1) ? sBlo : sBhi;
        const __nv_bfloat16* Ab = A + (wm + g) * APAD + tg * 2;
        const __nv_bfloat16* Bb = B + (wn + g) * APAD + tg * 2;
        #pragma unroll 1
        for (int ks = 0; ks < 8; ks++) {
            const int k0 = ks * 16;
            uint32_t a[2][4], b[8][2];
            #pragma unroll
            for (int mt = 0; mt < 2; mt++) {
                const __nv_bfloat16* p = Ab + mt * (16 * APAD) + k0;
                a[mt][0] = *(const uint32_t*)(p);
                a[mt][1] = *(const uint32_t*)(p + 8 * APAD);
                a[mt][2] = *(const uint32_t*)(p + 8);
                a[mt][3] = *(const uint32_t*)(p + 8 * APAD + 8);
            }
            #pragma unroll
            for (int nt = 0; nt < 8; nt++) {
                const __nv_bfloat16* p = Bb + nt * (8 * APAD) + k0;
                b[nt][0] = *(const uint32_t*)(p);
                b[nt][1] = *(const uint32_t*)(p + 8);
            }
            #pragma unroll
            for (int mt = 0; mt < 2; mt++)
                #pragma unroll
                for (int nt = 0; nt < 8; nt++)
                    MMA16816(acc[mt][nt], a[mt], b[nt]);
        }
    }

    // ---- epilogue: write X@W ----
    #pragma unroll
    for (int mt = 0; mt < 2; mt++) {
        size_t r0 = (size_t)(brow + wm + mt * 16 + g) * 128;
        size_t r1 = r0 + 8 * 128;
        #pragma unroll
        for (int nt = 0; nt < 8; nt++) {
            int c = wn + nt * 8 + tg * 2;
            *(float2*)&g_fused[r0 + c] = make_float2(acc[mt][nt][0], acc[mt][nt][1]);
            *(float2*)&g_fused[r1 + c] = make_float2(acc[mt][nt][2], acc[mt][nt][3]);
        }
    }
}

// =====================================================================
// pstats: per-block channel partials of (fused + T4[bidx])
// =====================================================================
__global__ void __launch_bounds__(256)
pstats_kernel(const int* __restrict__ bidx) {
    __shared__ float sT4[512];
    __shared__ int sB[256];
    __shared__ float rs[256], rq[256];
    const int tid = threadIdx.x;
    const int brow = blockIdx.x * GEMM_ROWS;
    for (int i = tid; i < 512; i += 256) sT4[i] = g_T4[i];
    sB[tid] = bidx[brow + tid];
    __syncthreads();

    const int c = tid & 127, half = tid >> 7;
    float s = 0.f, q = 0.f;
    #pragma unroll 4
    for (int r = half; r < 256; r += 2) {
        float v = g_fused[(size_t)(brow + r) * 128 + c] + sT4[sB[r] * 128 + c];
        s += v; q += v * v;
    }
    rs[tid] = s; rq[tid] = q;
    __syncthreads();
    if (tid < 128) {
        s = rs[tid] + rs[tid + 128];
        q = rq[tid] + rq[tid + 128];
        g_partial[tid * GEMM_BLOCKS + blockIdx.x]   = s;
        g_partialsq[tid * GEMM_BLOCKS + blockIdx.x] = q;
    }
}

// =====================================================================
// stats: reduce partials -> BN scale/shift (deterministic)
// =====================================================================
__global__ void stats_kernel(const float* __restrict__ gamma,
                             const float* __restrict__ beta) {
    const int c = blockIdx.x;
    const int tid = threadIdx.x;
    __shared__ float rs[256], rq[256];
    float s = 0.f, q = 0.f;
    for (int b = tid; b < GEMM_BLOCKS; b += 256) {
        s += g_partial[c * GEMM_BLOCKS + b];
        q += g_partialsq[c * GEMM_BLOCKS + b];
    }
    rs[tid] = s; rq[tid] = q;
    __syncthreads();
    for (int o = 128; o > 0; o >>= 1) {
        if (tid < o) { rs[tid] += rs[tid + o]; rq[tid] += rq[tid + o]; }
        __syncthreads();
    }
    if (tid == 0) {
        float mu  = rs[0] / (float)N_PTS;
        float var = rq[0] / (float)N_PTS - mu * mu;
        float sc  = gamma[c] * rsqrtf(var + 1e-5f);
        g_scale[c] = sc;
        g_shift[c] = beta[c] - mu * sc;
    }
}

// =====================================================================
// head2: x = relu(BN(fused + T4[bidx])); preds
// =====================================================================
__global__ void __launch_bounds__(256)
head2_kernel(const int* __restrict__ bidx,
             const float* __restrict__ Wb, const float* __restrict__ bb,
             const float* __restrict__ Wc, const float* __restrict__ bc,
             float* __restrict__ out) {
    __shared__ float4 sw[9][32];
    __shared__ float4 ssc[32], ssh[32];
    __shared__ float sb[9];
    __shared__ __align__(16) float sT4[512];
    const int tid = threadIdx.x;
    for (int i = tid; i < 288; i += 256) {
        int j = i >> 5, k4 = i & 31, k = k4 * 4;
        float4 w;
        if (j < 7) w = make_float4(Wb[(k+0)*7+j], Wb[(k+1)*7+j], Wb[(k+2)*7+j], Wb[(k+3)*7+j]);
        else { int jc = j - 7;
               w = make_float4(Wc[(k+0)*2+jc], Wc[(k+1)*2+jc], Wc[(k+2)*2+jc], Wc[(k+3)*2+jc]); }
        sw[j][k4] = w;
    }
    for (int i = tid; i < 512; i += 256) sT4[i] = g_T4[i];
    if (tid < 32) { ssc[tid] = ((const float4*)g_scale)[tid]; ssh[tid] = ((const float4*)g_shift)[tid]; }
    if (tid < 9) sb[tid] = (tid < 7) ? bb[tid] : bc[tid - 7];
    __syncthreads();

    const int p = blockIdx.x * 256 + tid;
    const int bofs = bidx[p] * 32;       // float4 index into sT4
    float acc[9];
    #pragma unroll
    for (int j = 0; j < 9; j++) acc[j] = sb[j];
    const float4* gf = (const float4*)g_fused;
    const float4* t4f = (const float4*)sT4;
    #pragma unroll 4
    for (int k4 = 0; k4 < 32; k4++) {
        float4 f = gf[(size_t)p * 32 + k4];
        float4 t = t4f[bofs + k4];
        float4 sc = ssc[k4], sh = ssh[k4];
        float x0 = fmaxf(fmaf(f.x + t.x, sc.x, sh.x), 0.f);
        float x1 = fmaxf(fmaf(f.y + t.y, sc.y, sh.y), 0.f);
        float x2 = fmaxf(fmaf(f.z + t.z, sc.z, sh.z), 0.f);
        float x3 = fmaxf(fmaf(f.w + t.w, sc.w, sh.w), 0.f);
        #pragma unroll
        for (int j = 0; j < 9; j++) {
            float4 w = sw[j][k4];
            acc[j] = fmaf(x0, w.x, acc[j]);
            acc[j] = fmaf(x1, w.y, acc[j]);
            acc[j] = fmaf(x2, w.z, acc[j]);
            acc[j] = fmaf(x3, w.w, acc[j]);
        }
    }
    float* o = out + (size_t)p * 9;
    o[0] = acc[0]; o[1] = acc[1]; o[2] = acc[2];
    o[3] = expf(acc[3]); o[4] = expf(acc[4]); o[5] = expf(acc[5]);
    o[6] = acc[6]; o[7] = acc[7]; o[8] = acc[8];
}

// ===================== assignment path (unchanged) =====================
__global__ void zero_cnt_kernel() { g_cnt[threadIdx.x] = 0; }

__global__ void __launch_bounds__(256)
cand_kernel(const float* __restrict__ p0, const float* __restrict__ p1,
            const float* __restrict__ boxes, const int* __restrict__ labels) {
    __shared__ float4 sc0[NG], sc1[NG];
    const int tid = threadIdx.x;
    if (tid < NG) {
        float cx = boxes[tid * 7 + 0], cy = boxes[tid * 7 + 1], cz = boxes[tid * 7 + 2];
        int lvl = labels[tid];
        sc0[tid] = make_float4(cx, cy, cz, (lvl == 0) ? R2_L0 : -1.0f);
        sc1[tid] = make_float4(cx, cy, cz, (lvl == 1) ? R2_L1 : -1.0f);
    }
    __syncthreads();

    const int p = blockIdx.x * 256 + tid;
    float px, py, pz; const float4* Cc;
    if (p < NL0) { px = p0[3 * p]; py = p0[3 * p + 1]; pz = p0[3 * p + 2]; Cc = sc0; }
    else { int q = p - NL0; px = p1[3 * q]; py = p1[3 * q + 1]; pz = p1[3 * q + 2]; Cc = sc1; }

    #pragma unroll 4
    for (int g = 0; g < NG; g++) {
        float4 c = Cc[g];
        float dx = px - c.x, dy = py - c.y, dz = pz - c.z;
        float d2 = fmaf(dz, dz, fmaf(dy, dy, dx * dx));
        if (d2 < c.w) {
            int idx = atomicAdd(&g_cnt[g], 1);
            if (idx < CAND_CAP) g_cand[(size_t)g * CAND_CAP + idx] = d2;
        }
    }
}

#define NBUCK 4096
#define BSCALE 235.0f
#define BCANDMAX 2048
#define KSEL 33

__global__ void __launch_bounds__(512)
select_kernel(const float* __restrict__ p0, const float* __restrict__ p1,
              const float* __restrict__ boxes, const int* __restrict__ labels) {
    const int g = blockIdx.x;
    const int tid = threadIdx.x;
    __shared__ unsigned hist[NBUCK];
    __shared__ unsigned csum[512];
    __shared__ float bcand[BCANDMAX];
    __shared__ int sInfo[3];

    const int lvl = labels[g];
    const float* pts = lvl ? p1 : p0;
    const int n = lvl ? NL1 : NL0;
    const float cx = boxes[g * 7 + 0], cy = boxes[g * 7 + 1], cz = boxes[g * 7 + 2];

    const int cnt = g_cnt[g];
    const bool ok = (cnt >= KSEL && cnt <= CAND_CAP);
    const float* src = &g_cand[(size_t)g * CAND_CAP];
    const int m = ok ? cnt : n;

    for (int i = tid; i < NBUCK; i += 512) hist[i] = 0u;
    if (tid == 0) sInfo[2] = 0;
    __syncthreads();

    for (int i = tid; i < m; i += 512) {
        float d2;
        if (ok) d2 = src[i];
        else {
            float dx = pts[3 * i] - cx, dy = pts[3 * i + 1] - cy, dz = pts[3 * i + 2] - cz;
            d2 = fmaf(dz, dz, fmaf(dy, dy, dx * dx));
        }
        int b = (int)(sqrtf(d2) * BSCALE); b = b > (NBUCK - 1) ? (NBUCK - 1) : b;
        atomicAdd(&hist[b], 1u);
    }
    __syncthreads();

    unsigned cs = 0;
    #pragma unroll
    for (int i = 0; i < 8; i++) cs += hist[tid * 8 + i];
    csum[tid] = cs;
    __syncthreads();
    if (tid == 0) {
        unsigned run = 0; int chunk = 0;
        while (chunk < 512 && run + csum[chunk] < KSEL) { run += csum[chunk]; chunk++; }
        int B = chunk * 8;
        while (run + hist[B] < KSEL) { run += hist[B]; B++; }
        sInfo[0] = B; sInfo[1] = (int)run;
    }
    __syncthreads();
    const int B = sInfo[0];

    for (int i = tid; i < m; i += 512) {
        float d2;
        if (ok) d2 = src[i];
        else {
            float dx = pts[3 * i] - cx, dy = pts[3 * i + 1] - cy, dz = pts[3 * i + 2] - cz;
            d2 = fmaf(dz, dz, fmaf(dy, dy, dx * dx));
        }
        int b = (int)(sqrtf(d2) * BSCALE); b = b > (NBUCK - 1) ? (NBUCK - 1) : b;
        if (b == B) {
            int pos = atomicAdd(&sInfo[2], 1);
            if (pos < BCANDMAX) bcand[pos] = d2;
        }
    }
    __syncthreads();
    if (tid == 0) {
        int mb = sInfo[2]; if (mb > BCANDMAX) mb = BCANDMAX;
        int need = KSEL - sInfo[1];
        float kth = 1e8f;
        for (int r = 0; r < need; r++) {
            float best = 3.4e38f; int bi = 0;
            for (int i = 0; i < mb; i++) { float v = bcand[i]; if (v < best) { best = v; bi = i; } }
            kth = best; bcand[bi] = 3.4e38f;
        }
        g_kth[g] = kth;
    }
}

__global__ void __launch_bounds__(256)
assign_kernel(const float* __restrict__ p0, const float* __restrict__ p1,
              const float* __restrict__ boxes, const int* __restrict__ labels,
              float* __restrict__ out) {
    __shared__ float4 sc0[NG], sc1[NG];
    const int tid = threadIdx.x;
    if (tid < NG) {
        float cx = boxes[tid * 7 + 0], cy = boxes[tid * 7 + 1], cz = boxes[tid * 7 + 2];
        int lvl = labels[tid];
        float kth = g_kth[tid];
        sc0[tid] = make_float4(cx, cy, cz, (lvl == 0) ? kth : -1.0f);
        sc1[tid] = make_float4(cx, cy, cz, (lvl == 1) ? kth : -1.0f);
    }
    __syncthreads();

    const int p = blockIdx.x * 256 + tid;
    float px, py, pz; const float4* Cc;
    if (p < NL0) { px = p0[3 * p]; py = p0[3 * p + 1]; pz = p0[3 * p + 2]; Cc = sc0; }
    else { int q = p - NL0; px = p1[3 * q]; py = p1[3 * q + 1]; pz = p1[3 * q + 2]; Cc = sc1; }

    float best = 3.4e38f; int bi = 0;
    float gbest = 1e8f;   int gi = -1;
    #pragma unroll 4
    for (int g = 0; g < NG; g++) {
        float4 c = Cc[g];
        float dx = px - c.x, dy = py - c.y, dz = pz - c.z;
        float d2 = fmaf(dz, dz, fmaf(dy, dy, dx * dx));
        if (d2 < best) { best = d2; bi = g; }
        if (d2 < c.w && d2 < gbest) { gbest = d2; gi = g; }
    }
    int a = (gi == bi) ? gi : -1;
    out[(size_t)N_PTS * 9 + p] = (float)a;
}

// =====================================================================
// launch — gemm moved to 4th position so ncu profiles it
// =====================================================================
extern "C" void kernel_launch(void* const* d_in, const int* in_sizes, int n_in,
                              void* d_out, int out_size) {
    const float* bf    = (const float*)d_in[0];
    const float* text  = (const float*)d_in[1];
    const float* Wf    = (const float*)d_in[2];
    const float* bfu   = (const float*)d_in[3];
    const float* gamma = (const float*)d_in[4];
    const float* beta  = (const float*)d_in[5];
    const float* Wb    = (const float*)d_in[6];
    const float* bb    = (const float*)d_in[7];
    const float* Wc    = (const float*)d_in[8];
    const float* bc    = (const float*)d_in[9];
    const float* p0    = (const float*)d_in[10];
    const float* p1    = (const float*)d_in[11];
    const bool sig = (in_sizes[12] == 128 * 7);
    const float* boxes  = (const float*)d_in[sig ? 12 : 14];
    const int*   bidx   = (const int*)  d_in[sig ? 13 : 12];
    const int*   labels = (const int*)  d_in[sig ? 14 : 13];
    float* out = (float*)d_out;

    cudaFuncSetAttribute(gemm_kernel, cudaFuncAttributeMaxDynamicSharedMemorySize,
                         GEMM_SMEM);

    wprep_kernel<<<64, 256>>>(Wf);                       // 1
    t4_kernel<<<1, 512>>>(text, Wf, bfu);                // 2
    zero_cnt_kernel<<<1, NG>>>();                        // 3
    gemm_kernel<<<GEMM_BLOCKS, 512, GEMM_SMEM>>>(bf);    // 4  <- profiled
    cand_kernel<<<N_PTS / 256, 256>>>(p0, p1, boxes, labels);   // 5
    select_kernel<<<NG, 512>>>(p0, p1, boxes, labels);   // 6
    assign_kernel<<<N_PTS / 256, 256>>>(p0, p1, boxes, labels, out);  // 7
    pstats_kernel<<<GEMM_BLOCKS, 256>>>(bidx);           // 8
    stats_kernel<<<128, 256>>>(gamma, beta);             // 9
    head2_kernel<<<N_PTS / 256, 256>>>(bidx, Wb, bb, Wc, bc, out);    // 10
}

// round 14
// speedup vs baseline: 1.6148x; 1.1154x over previous
#include <cuda_runtime.h>
#include <cuda_bf16.h>
#include <math.h>
#include <stdint.h>

// ---------------- problem constants (fixed shapes) ----------------
#define N_PTS    160000
#define NL0      100000
#define NL1       60000
#define NG       128
#define NC       128
#define GEMM_ROWS 256
#define GEMM_BLOCKS (N_PTS / GEMM_ROWS)   // 625

// ---------------- device scratch (no allocation allowed) ----------------
__device__ float g_fused[(size_t)N_PTS * NC];           // X @ W + T4[bidx]
__device__ float g_T4[4 * NC];
__device__ __align__(16) __nv_bfloat16 g_Whi[NC * NC];  // [n][k] = bf16(W[k][n])
__device__ __align__(16) __nv_bfloat16 g_Wlo[NC * NC];  // residual
__device__ float g_partial[NC * GEMM_BLOCKS];
__device__ float g_partialsq[NC * GEMM_BLOCKS];
__device__ __align__(16) float g_scale[NC];
__device__ __align__(16) float g_shift[NC];
__device__ float g_kth[NG];
__device__ int   g_bi[N_PTS];                           // per-point global argmin
__device__ float g_bd[N_PTS];                           // its d2

#define CAND_CAP 2048
__device__ float g_cand[(size_t)NG * CAND_CAP];
__device__ int   g_cnt[NG];

#define R2_L0 1.44f
#define R2_L1 2.25f

// ---------------- mma.sync bf16 (baseline PTX, works on sm_103) ------
#define MMA16816(d, a, b) \
    asm volatile("mma.sync.aligned.m16n8k16.row.col.f32.bf16.bf16.f32 " \
        "{%0,%1,%2,%3}, {%4,%5,%6,%7}, {%8,%9}, {%0,%1,%2,%3};" \
        : "+f"((d)[0]), "+f"((d)[1]), "+f"((d)[2]), "+f"((d)[3]) \
        : "r"((a)[0]), "r"((a)[1]), "r"((a)[2]), "r"((a)[3]), \
          "r"((b)[0]), "r"((b)[1]))

#define CVT_BF16X2(res, a, b) \
    asm("cvt.rn.bf16x2.f32 %0, %1, %2;" : "=r"(res) : "f"(b), "f"(a))

__device__ __forceinline__ void split2(float a, float b, uint32_t& hp, uint32_t& lp) {
    CVT_BF16X2(hp, a, b);
    float ha = __uint_as_float(hp << 16);
    float hb = __uint_as_float(hp & 0xffff0000u);
    float ra = a - ha, rb = b - hb;
    CVT_BF16X2(lp, ra, rb);
}

// gemm smem layout: padded rows of 136 bf16 (272 B)
#define APAD 136
#define SM_BHI 0
#define SM_BLO (SM_BHI + 128 * APAD * 2)      // 34816
#define SM_AHI (SM_BLO + 128 * APAD * 2)      // 69632
#define SM_ALO (SM_AHI + 256 * APAD * 2)      // 139264
#define SM_T4  (SM_ALO + 256 * APAD * 2)      // 208896, float[512]
#define SM_BIDX (SM_T4 + 2048)                // 210944, int[256]
#define GEMM_SMEM (SM_BIDX + 1024)            // 211968 (~207 KB)

// =====================================================================
// prep: blocks 0..63 = W split; block 64 = T4 + zero cnt
// =====================================================================
__global__ void prep_kernel(const float* __restrict__ Wf,
                            const float* __restrict__ text,
                            const float* __restrict__ bfuse) {
    const int tid = threadIdx.x;
    if (blockIdx.x < 64) {
        int i = blockIdx.x * 256 + tid;       // 16384
        int n = i >> 7, k = i & 127;
        float v = Wf[k * 128 + n];
        __nv_bfloat16 h = __float2bfloat16(v);
        float r = v - __bfloat162float(h);
        g_Whi[n * 128 + k] = h;
        g_Wlo[n * 128 + k] = __float2bfloat16(r);
    } else {
        if (tid < NG) g_cnt[tid] = 0;
        for (int u = tid; u < 512; u += 256) {
            int t = u >> 7, c = u & 127;
            float acc = bfuse[c];
            #pragma unroll 8
            for (int k = 0; k < 128; k++)
                acc = fmaf(text[t * 128 + k], Wf[(128 + k) * 128 + c], acc);
            g_T4[u] = acc;
        }
    }
}

// =====================================================================
// GEMM: g_fused = X @ W + T4[bidx]; fused per-block BN partial stats.
// 256x128 tile, 16 warps (8 row-strips x 2 col-strips), warp tile 32x64.
// =====================================================================
__global__ void __launch_bounds__(512, 1)
gemm_kernel(const float* __restrict__ bf, const int* __restrict__ bidx) {
    extern __shared__ char smem[];
    __nv_bfloat16* sBhi = (__nv_bfloat16*)(smem + SM_BHI);
    __nv_bfloat16* sBlo = (__nv_bfloat16*)(smem + SM_BLO);
    __nv_bfloat16* sAhi = (__nv_bfloat16*)(smem + SM_AHI);
    __nv_bfloat16* sAlo = (__nv_bfloat16*)(smem + SM_ALO);
    float* sT4 = (float*)(smem + SM_T4);
    int*   sBi = (int*)(smem + SM_BIDX);

    const int tid  = threadIdx.x;
    const int warp = tid >> 5;
    const int lane = tid & 31;
    const int g  = lane >> 2;          // 0..7
    const int tg = lane & 3;           // 0..3
    const int brow = blockIdx.x * GEMM_ROWS;

    // ---- load B (W^T hi/lo) into padded smem rows (threads 0..255) ----
    if (tid < 256) {
        int n = tid & 127;
        const uint4* src = (const uint4*)((tid < 128 ? g_Whi : g_Wlo) + n * 128);
        __nv_bfloat16* dst = (tid < 128 ? sBhi : sBlo) + n * APAD;
        #pragma unroll
        for (int j = 0; j < 16; j++)
            *(uint4*)(dst + j * 8) = src[j];
    }
    sT4[tid] = g_T4[tid];
    if (tid < 256) sBi[tid] = bidx[brow + tid];

    // ---- load + convert X tile (coalesced, all 512 threads) ----
    {
        const float4* bf4 = (const float4*)bf;
        #pragma unroll 4
        for (int it = 0; it < 16; it++) {
            int idx = it * 512 + tid;            // 8192 float4s
            int r = idx >> 5, c4 = idx & 31;
            float4 v = bf4[(size_t)(brow + r) * 32 + c4];
            uint32_t h0, l0, h1, l1;
            split2(v.x, v.y, h0, l0);
            split2(v.z, v.w, h1, l1);
            *(uint2*)(sAhi + r * APAD + c4 * 4) = make_uint2(h0, h1);
            *(uint2*)(sAlo + r * APAD + c4 * 4) = make_uint2(l0, l1);
        }
    }
    __syncthreads();

    const int wm = (warp & 7) * 32;    // row offset (8 strips)
    const int wn = (warp >> 3) * 64;   // col offset (2 strips)

    float acc[2][8][4];
    #pragma unroll
    for (int mt = 0; mt < 2; mt++)
        #pragma unroll
        for (int nt = 0; nt < 8; nt++)
            #pragma unroll
            for (int r = 0; r < 4; r++) acc[mt][nt][r] = 0.f;

    #pragma unroll 1
    for (int pass = 0; pass < 3; pass++) {
        const __nv_bfloat16* A = (pass == 2) ? sAlo : sAhi;
        const __nv_bfloat16* B = (pass == 1) ? sBlo : sBhi;
        const __nv_bfloat16* Ab = A + (wm + g) * APAD + tg * 2;
        const __nv_bfloat16* Bb = B + (wn + g) * APAD + tg * 2;
        #pragma unroll 1
        for (int ks = 0; ks < 8; ks++) {
            const int k0 = ks * 16;
            uint32_t a[2][4], b[8][2];
            #pragma unroll
            for (int mt = 0; mt < 2; mt++) {
                const __nv_bfloat16* p = Ab + mt * (16 * APAD) + k0;
                a[mt][0] = *(const uint32_t*)(p);
                a[mt][1] = *(const uint32_t*)(p + 8 * APAD);
                a[mt][2] = *(const uint32_t*)(p + 8);
                a[mt][3] = *(const uint32_t*)(p + 8 * APAD + 8);
            }
            #pragma unroll
            for (int nt = 0; nt < 8; nt++) {
                const __nv_bfloat16* p = Bb + nt * (8 * APAD) + k0;
                b[nt][0] = *(const uint32_t*)(p);
                b[nt][1] = *(const uint32_t*)(p + 8);
            }
            #pragma unroll
            for (int mt = 0; mt < 2; mt++)
                #pragma unroll
                for (int nt = 0; nt < 8; nt++)
                    MMA16816(acc[mt][nt], a[mt], b[nt]);
        }
    }

    // ---- epilogue: +T4, store, per-column stats (reuse sBhi as buffers) ----
    __syncthreads();   // all B reads done
    float* bufS = (float*)(smem + SM_BHI);   // [128][8]
    float* bufQ = bufS + 1024;
    const int w8 = warp & 7;
    #pragma unroll
    for (int nt = 0; nt < 8; nt++) {
        const int c0 = wn + nt * 8 + tg * 2;
        float s0 = 0.f, q0 = 0.f, s1 = 0.f, q1 = 0.f;
        #pragma unroll
        for (int mt = 0; mt < 2; mt++) {
            int rA = wm + mt * 16 + g, rB = rA + 8;
            float2 tA = *(float2*)&sT4[sBi[rA] * 128 + c0];
            float2 tB = *(float2*)&sT4[sBi[rB] * 128 + c0];
            float v0 = acc[mt][nt][0] + tA.x, v1 = acc[mt][nt][1] + tA.y;
            float v2 = acc[mt][nt][2] + tB.x, v3 = acc[mt][nt][3] + tB.y;
            *(float2*)&g_fused[(size_t)(brow + rA) * 128 + c0] = make_float2(v0, v1);
            *(float2*)&g_fused[(size_t)(brow + rB) * 128 + c0] = make_float2(v2, v3);
            s0 += v0 + v2; s1 += v1 + v3;
            q0 += v0 * v0 + v2 * v2; q1 += v1 * v1 + v3 * v3;
        }
        #pragma unroll
        for (int off = 16; off >= 4; off >>= 1) {
            s0 += __shfl_xor_sync(0xffffffffu, s0, off);
            s1 += __shfl_xor_sync(0xffffffffu, s1, off);
            q0 += __shfl_xor_sync(0xffffffffu, q0, off);
            q1 += __shfl_xor_sync(0xffffffffu, q1, off);
        }
        if (g == 0) {
            bufS[c0 * 8 + w8] = s0; bufS[(c0 + 1) * 8 + w8] = s1;
            bufQ[c0 * 8 + w8] = q0; bufQ[(c0 + 1) * 8 + w8] = q1;
        }
    }
    __syncthreads();
    if (tid < 128) {
        float s = 0.f, q = 0.f;
        #pragma unroll
        for (int i = 0; i < 8; i++) { s += bufS[tid * 8 + i]; q += bufQ[tid * 8 + i]; }
        g_partial[tid * GEMM_BLOCKS + blockIdx.x]   = s;
        g_partialsq[tid * GEMM_BLOCKS + blockIdx.x] = q;
    }
}

// =====================================================================
// stats: reduce partials -> BN scale/shift (deterministic)
// =====================================================================
__global__ void stats_kernel(const float* __restrict__ gamma,
                             const float* __restrict__ beta) {
    const int c = blockIdx.x;
    const int tid = threadIdx.x;
    __shared__ float rs[256], rq[256];
    float s = 0.f, q = 0.f;
    for (int b = tid; b < GEMM_BLOCKS; b += 256) {
        s += g_partial[c * GEMM_BLOCKS + b];
        q += g_partialsq[c * GEMM_BLOCKS + b];
    }
    rs[tid] = s; rq[tid] = q;
    __syncthreads();
    for (int o = 128; o > 0; o >>= 1) {
        if (tid < o) { rs[tid] += rs[tid + o]; rq[tid] += rq[tid + o]; }
        __syncthreads();
    }
    if (tid == 0) {
        float mu  = rs[0] / (float)N_PTS;
        float var = rq[0] / (float)N_PTS - mu * mu;
        float sc  = gamma[c] * rsqrtf(var + 1e-5f);
        g_scale[c] = sc;
        g_shift[c] = beta[c] - mu * sc;
    }
}

// =====================================================================
// head2: x = relu(BN(fused)); preds   (g_fused already includes T4)
// =====================================================================
__global__ void __launch_bounds__(256)
head2_kernel(const float* __restrict__ Wb, const float* __restrict__ bb,
             const float* __restrict__ Wc, const float* __restrict__ bc,
             float* __restrict__ out) {
    __shared__ float4 sw[9][32];
    __shared__ float4 ssc[32], ssh[32];
    __shared__ float sb[9];
    const int tid = threadIdx.x;
    for (int i = tid; i < 288; i += 256) {
        int j = i >> 5, k4 = i & 31, k = k4 * 4;
        float4 w;
        if (j < 7) w = make_float4(Wb[(k+0)*7+j], Wb[(k+1)*7+j], Wb[(k+2)*7+j], Wb[(k+3)*7+j]);
        else { int jc = j - 7;
               w = make_float4(Wc[(k+0)*2+jc], Wc[(k+1)*2+jc], Wc[(k+2)*2+jc], Wc[(k+3)*2+jc]); }
        sw[j][k4] = w;
    }
    if (tid < 32) { ssc[tid] = ((const float4*)g_scale)[tid]; ssh[tid] = ((const float4*)g_shift)[tid]; }
    if (tid < 9) sb[tid] = (tid < 7) ? bb[tid] : bc[tid - 7];
    __syncthreads();

    const int p = blockIdx.x * 256 + tid;
    float acc[9];
    #pragma unroll
    for (int j = 0; j < 9; j++) acc[j] = sb[j];
    const float4* gf = (const float4*)g_fused;
    #pragma unroll 4
    for (int k4 = 0; k4 < 32; k4++) {
        float4 f = gf[(size_t)p * 32 + k4];
        float4 sc = ssc[k4], sh = ssh[k4];
        float x0 = fmaxf(fmaf(f.x, sc.x, sh.x), 0.f);
        float x1 = fmaxf(fmaf(f.y, sc.y, sh.y), 0.f);
        float x2 = fmaxf(fmaf(f.z, sc.z, sh.z), 0.f);
        float x3 = fmaxf(fmaf(f.w, sc.w, sh.w), 0.f);
        #pragma unroll
        for (int j = 0; j < 9; j++) {
            float4 w = sw[j][k4];
            acc[j] = fmaf(x0, w.x, acc[j]);
            acc[j] = fmaf(x1, w.y, acc[j]);
            acc[j] = fmaf(x2, w.z, acc[j]);
            acc[j] = fmaf(x3, w.w, acc[j]);
        }
    }
    float* o = out + (size_t)p * 9;
    o[0] = acc[0]; o[1] = acc[1]; o[2] = acc[2];
    o[3] = expf(acc[3]); o[4] = expf(acc[4]); o[5] = expf(acc[5]);
    o[6] = acc[6]; o[7] = acc[7]; o[8] = acc[8];
}

// =====================================================================
// cand: candidates within radius + per-point global argmin (bi, d2)
// =====================================================================
__global__ void __launch_bounds__(256)
cand_kernel(const float* __restrict__ p0, const float* __restrict__ p1,
            const float* __restrict__ boxes, const int* __restrict__ labels) {
    __shared__ float4 sc0[NG], sc1[NG];
    const int tid = threadIdx.x;
    if (tid < NG) {
        float cx = boxes[tid * 7 + 0], cy = boxes[tid * 7 + 1], cz = boxes[tid * 7 + 2];
        int lvl = labels[tid];
        sc0[tid] = make_float4(cx, cy, cz, (lvl == 0) ? R2_L0 : -1.0f);
        sc1[tid] = make_float4(cx, cy, cz, (lvl == 1) ? R2_L1 : -1.0f);
    }
    __syncthreads();

    const int p = blockIdx.x * 256 + tid;
    float px, py, pz; const float4* Cc;
    if (p < NL0) { px = p0[3 * p]; py = p0[3 * p + 1]; pz = p0[3 * p + 2]; Cc = sc0; }
    else { int q = p - NL0; px = p1[3 * q]; py = p1[3 * q + 1]; pz = p1[3 * q + 2]; Cc = sc1; }

    float best = 3.4e38f; int bi = 0;       // global argmin (first occurrence)
    #pragma unroll 4
    for (int g = 0; g < NG; g++) {
        float4 c = Cc[g];
        float dx = px - c.x, dy = py - c.y, dz = pz - c.z;
        float d2 = fmaf(dz, dz, fmaf(dy, dy, dx * dx));
        if (d2 < best) { best = d2; bi = g; }
        if (d2 < c.w) {
            int idx = atomicAdd(&g_cnt[g], 1);
            if (idx < CAND_CAP) g_cand[(size_t)g * CAND_CAP + idx] = d2;
        }
    }
    g_bi[p] = bi;
    g_bd[p] = best;
}

// =====================================================================
// select: exact 33rd-smallest per gt (candidates; full-scan fallback)
// =====================================================================
#define NBUCK 4096
#define BSCALE 235.0f
#define BCANDMAX 2048
#define KSEL 33

__global__ void __launch_bounds__(512)
select_kernel(const float* __restrict__ p0, const float* __restrict__ p1,
              const float* __restrict__ boxes, const int* __restrict__ labels) {
    const int g = blockIdx.x;
    const int tid = threadIdx.x;
    __shared__ unsigned hist[NBUCK];
    __shared__ unsigned csum[512];
    __shared__ float bcand[BCANDMAX];
    __shared__ int sInfo[3];

    const int lvl = labels[g];
    const float* pts = lvl ? p1 : p0;
    const int n = lvl ? NL1 : NL0;
    const float cx = boxes[g * 7 + 0], cy = boxes[g * 7 + 1], cz = boxes[g * 7 + 2];

    const int cnt = g_cnt[g];
    const bool ok = (cnt >= KSEL && cnt <= CAND_CAP);
    const float* src = &g_cand[(size_t)g * CAND_CAP];
    const int m = ok ? cnt : n;

    for (int i = tid; i < NBUCK; i += 512) hist[i] = 0u;
    if (tid == 0) sInfo[2] = 0;
    __syncthreads();

    for (int i = tid; i < m; i += 512) {
        float d2;
        if (ok) d2 = src[i];
        else {
            float dx = pts[3 * i] - cx, dy = pts[3 * i + 1] - cy, dz = pts[3 * i + 2] - cz;
            d2 = fmaf(dz, dz, fmaf(dy, dy, dx * dx));
        }
        int b = (int)(sqrtf(d2) * BSCALE); b = b > (NBUCK - 1) ? (NBUCK - 1) : b;
        atomicAdd(&hist[b], 1u);
    }
    __syncthreads();

    unsigned cs = 0;
    #pragma unroll
    for (int i = 0; i < 8; i++) cs += hist[tid * 8 + i];
    csum[tid] = cs;
    __syncthreads();
    if (tid == 0) {
        unsigned run = 0; int chunk = 0;
        while (chunk < 512 && run + csum[chunk] < KSEL) { run += csum[chunk]; chunk++; }
        int B = chunk * 8;
        while (run + hist[B] < KSEL) { run += hist[B]; B++; }
        sInfo[0] = B; sInfo[1] = (int)run;
    }
    __syncthreads();
    const int B = sInfo[0];

    for (int i = tid; i < m; i += 512) {
        float d2;
        if (ok) d2 = src[i];
        else {
            float dx = pts[3 * i] - cx, dy = pts[3 * i + 1] - cy, dz = pts[3 * i + 2] - cz;
            d2 = fmaf(dz, dz, fmaf(dy, dy, dx * dx));
        }
        int b = (int)(sqrtf(d2) * BSCALE); b = b > (NBUCK - 1) ? (NBUCK - 1) : b;
        if (b == B) {
            int pos = atomicAdd(&sInfo[2], 1);
            if (pos < BCANDMAX) bcand[pos] = d2;
        }
    }
    __syncthreads();
    if (tid == 0) {
        int mb = sInfo[2]; if (mb > BCANDMAX) mb = BCANDMAX;
        int need = KSEL - sInfo[1];
        float kth = 1e8f;
        for (int r = 0; r < need; r++) {
            float best = 3.4e38f; int bi = 0;
            for (int i = 0; i < mb; i++) { float v = bcand[i]; if (v < best) { best = v; bi = i; } }
            kth = best; bcand[bi] = 3.4e38f;
        }
        g_kth[g] = kth;
    }
}

// =====================================================================
// finalize: result(p) = bi if (level[bi]==level(p) && d2_bi < kth[bi])
// =====================================================================
__global__ void __launch_bounds__(256)
finalize_kernel(const int* __restrict__ labels, float* __restrict__ out) {
    __shared__ float skth[NG];
    __shared__ int   slab[NG];
    const int tid = threadIdx.x;
    if (tid < NG) { skth[tid] = g_kth[tid]; slab[tid] = labels[tid]; }
    __syncthreads();
    const int p = blockIdx.x * 256 + tid;
    const int lvl = (p < NL0) ? 0 : 1;
    const int bi = g_bi[p];
    const float d2 = g_bd[p];
    int a = (slab[bi] == lvl && d2 < skth[bi]) ? bi : -1;
    out[(size_t)N_PTS * 9 + p] = (float)a;
}

// =====================================================================
// launch — gemm kept 4th so ncu profiles it
// =====================================================================
extern "C" void kernel_launch(void* const* d_in, const int* in_sizes, int n_in,
                              void* d_out, int out_size) {
    const float* bf    = (const float*)d_in[0];
    const float* text  = (const float*)d_in[1];
    const float* Wf    = (const float*)d_in[2];
    const float* bfu   = (const float*)d_in[3];
    const float* gamma = (const float*)d_in[4];
    const float* beta  = (const float*)d_in[5];
    const float* Wb    = (const float*)d_in[6];
    const float* bb    = (const float*)d_in[7];
    const float* Wc    = (const float*)d_in[8];
    const float* bc    = (const float*)d_in[9];
    const float* p0    = (const float*)d_in[10];
    const float* p1    = (const float*)d_in[11];
    const bool sig = (in_sizes[12] == 128 * 7);
    const float* boxes  = (const float*)d_in[sig ? 12 : 14];
    const int*   bidx   = (const int*)  d_in[sig ? 13 : 12];
    const int*   labels = (const int*)  d_in[sig ? 14 : 13];
    float* out = (float*)d_out;

    cudaFuncSetAttribute(gemm_kernel, cudaFuncAttributeMaxDynamicSharedMemorySize,
                         GEMM_SMEM);

    prep_kernel<<<65, 256>>>(Wf, text, bfu);                        // 1
    cand_kernel<<<N_PTS / 256, 256>>>(p0, p1, boxes, labels);       // 2
    select_kernel<<<NG, 512>>>(p0, p1, boxes, labels);              // 3
    gemm_kernel<<<GEMM_BLOCKS, 512, GEMM_SMEM>>>(bf, bidx);         // 4 <- profiled
    finalize_kernel<<<N_PTS / 256, 256>>>(labels, out);             // 5
    stats_kernel<<<128, 256>>>(gamma, beta);                        // 6
    head2_kernel<<<N_PTS / 256, 256>>>(Wb, bb, Wc, bc, out);        // 7
}

// round 15
// speedup vs baseline: 1.6638x; 1.0304x over previous
#include <cuda_runtime.h>
#include <cuda_bf16.h>
#include <math.h>
#include <stdint.h>

// ---------------- problem constants (fixed shapes) ----------------
#define N_PTS    160000
#define NL0      100000
#define NL1       60000
#define NG       128
#define NC       128
#define GEMM_ROWS 256
#define GEMM_BLOCKS (N_PTS / GEMM_ROWS)   // 625

// ---------------- device scratch (no allocation allowed) ----------------
__device__ float g_fused[(size_t)N_PTS * NC];           // X @ W + T4[bidx]
__device__ float g_T4[4 * NC];
__device__ __align__(16) __nv_bfloat16 g_Whi[NC * NC];  // [n][k] = bf16(W[k][n])
__device__ __align__(16) __nv_bfloat16 g_Wlo[NC * NC];  // residual
__device__ float g_partial[NC * GEMM_BLOCKS];
__device__ float g_partialsq[NC * GEMM_BLOCKS];
__device__ __align__(16) float g_scale[NC];
__device__ __align__(16) float g_shift[NC];
__device__ float g_kth[NG];
__device__ int   g_bi[N_PTS];                           // per-point global argmin
__device__ float g_bd[N_PTS];                           // its d2

#define CAND_CAP 2048
__device__ float g_cand[(size_t)NG * CAND_CAP];
__device__ int   g_cnt[NG];

#define R2_L0 1.44f
#define R2_L1 2.25f

// ---------------- mma.sync / ldmatrix (baseline PTX, sm_103-safe) ----
#define MMA16816(d, a, b0, b1) \
    asm volatile("mma.sync.aligned.m16n8k16.row.col.f32.bf16.bf16.f32 " \
        "{%0,%1,%2,%3}, {%4,%5,%6,%7}, {%8,%9}, {%0,%1,%2,%3};" \
        : "+f"((d)[0]), "+f"((d)[1]), "+f"((d)[2]), "+f"((d)[3]) \
        : "r"((a)[0]), "r"((a)[1]), "r"((a)[2]), "r"((a)[3]), \
          "r"(b0), "r"(b1))

#define LDSM4(r0, r1, r2, r3, addr) \
    asm volatile("ldmatrix.sync.aligned.m8n8.x4.shared.b16 {%0,%1,%2,%3}, [%4];" \
        : "=r"(r0), "=r"(r1), "=r"(r2), "=r"(r3) : "r"(addr))

#define CVT_BF16X2(res, a, b) \
    asm("cvt.rn.bf16x2.f32 %0, %1, %2;" : "=r"(res) : "f"(b), "f"(a))

__device__ __forceinline__ void split2(float a, float b, uint32_t& hp, uint32_t& lp) {
    CVT_BF16X2(hp, a, b);
    float ha = __uint_as_float(hp << 16);
    float hb = __uint_as_float(hp & 0xffff0000u);
    float ra = a - ha, rb = b - hb;
    CVT_BF16X2(lp, ra, rb);
}

__device__ __forceinline__ uint32_t smem_u32(const void* p) {
    uint32_t a;
    asm("{ .reg .u64 t; cvta.to.shared.u64 t, %1; cvt.u32.u64 %0, t; }"
        : "=r"(a) : "l"(p));
    return a;
}

// gemm smem layout: padded rows of 136 bf16 (272 B)
#define APAD 136
#define SM_BHI 0
#define SM_BLO (SM_BHI + 128 * APAD * 2)      // 34816
#define SM_AHI (SM_BLO + 128 * APAD * 2)      // 69632
#define SM_ALO (SM_AHI + 256 * APAD * 2)      // 139264
#define SM_T4  (SM_ALO + 256 * APAD * 2)      // 208896, float[512]
#define SM_BIDX (SM_T4 + 2048)                // 210944, int[256]
#define GEMM_SMEM (SM_BIDX + 1024)            // 211968 (~207 KB)

// =====================================================================
// prep: blocks 0..63 = W split; block 64 = T4 + zero cnt
// =====================================================================
__global__ void prep_kernel(const float* __restrict__ Wf,
                            const float* __restrict__ text,
                            const float* __restrict__ bfuse) {
    const int tid = threadIdx.x;
    if (blockIdx.x < 64) {
        int i = blockIdx.x * 256 + tid;       // 16384
        int n = i >> 7, k = i & 127;
        float v = Wf[k * 128 + n];
        __nv_bfloat16 h = __float2bfloat16(v);
        float r = v - __bfloat162float(h);
        g_Whi[n * 128 + k] = h;
        g_Wlo[n * 128 + k] = __float2bfloat16(r);
    } else {
        if (tid < NG) g_cnt[tid] = 0;
        for (int u = tid; u < 512; u += 256) {
            int t = u >> 7, c = u & 127;
            float acc = bfuse[c];
            #pragma unroll 8
            for (int k = 0; k < 128; k++)
                acc = fmaf(text[t * 128 + k], Wf[(128 + k) * 128 + c], acc);
            g_T4[u] = acc;
        }
    }
}

// =====================================================================
// GEMM: g_fused = X @ W + T4[bidx]; fused BN partial stats.
// 256x128 tile, 16 warps, warp tile 32x64; ldmatrix frag loads.
// =====================================================================
__global__ void __launch_bounds__(512, 1)
gemm_kernel(const float* __restrict__ bf, const int* __restrict__ bidx) {
    extern __shared__ char smem[];
    __nv_bfloat16* sBhi = (__nv_bfloat16*)(smem + SM_BHI);
    __nv_bfloat16* sBlo = (__nv_bfloat16*)(smem + SM_BLO);
    __nv_bfloat16* sAhi = (__nv_bfloat16*)(smem + SM_AHI);
    __nv_bfloat16* sAlo = (__nv_bfloat16*)(smem + SM_ALO);
    float* sT4 = (float*)(smem + SM_T4);
    int*   sBi = (int*)(smem + SM_BIDX);

    const int tid  = threadIdx.x;
    const int warp = tid >> 5;
    const int lane = tid & 31;
    const int g  = lane >> 2;          // 0..7
    const int tg = lane & 3;           // 0..3
    const int brow = blockIdx.x * GEMM_ROWS;

    // ---- load B (W^T hi/lo) into padded smem rows (threads 0..255) ----
    if (tid < 256) {
        int n = tid & 127;
        const uint4* src = (const uint4*)((tid < 128 ? g_Whi : g_Wlo) + n * 128);
        __nv_bfloat16* dst = (tid < 128 ? sBhi : sBlo) + n * APAD;
        #pragma unroll
        for (int j = 0; j < 16; j++)
            *(uint4*)(dst + j * 8) = src[j];
    }
    sT4[tid] = g_T4[tid];
    if (tid < 256) sBi[tid] = bidx[brow + tid];

    // ---- load + convert X tile (coalesced, all 512 threads) ----
    {
        const float4* bf4 = (const float4*)bf;
        #pragma unroll 4
        for (int it = 0; it < 16; it++) {
            int idx = it * 512 + tid;            // 8192 float4s
            int r = idx >> 5, c4 = idx & 31;
            float4 v = bf4[(size_t)(brow + r) * 32 + c4];
            uint32_t h0, l0, h1, l1;
            split2(v.x, v.y, h0, l0);
            split2(v.z, v.w, h1, l1);
            *(uint2*)(sAhi + r * APAD + c4 * 4) = make_uint2(h0, h1);
            *(uint2*)(sAlo + r * APAD + c4 * 4) = make_uint2(l0, l1);
        }
    }
    __syncthreads();

    const int wm = (warp & 7) * 32;    // row offset (8 strips)
    const int wn = (warp >> 3) * 64;   // col offset (2 strips)

    // ---- per-lane ldmatrix base addresses (hi buffers, ks = 0) ----
    // tile index = lane>>3: A: row_off = (t&1)*8, k_off = (t>>1)*8
    //              B: nt_off = (t>>1),   k_off = (t&1)*8
    const int grp = lane >> 3, lr = lane & 7;
    const uint32_t su = smem_u32(smem);
    uint32_t aab0, aab1, bab[4];
    {
        int arow = wm + (grp & 1) * 8 + lr;
        int akc  = (grp >> 1) * 8;
        aab0 = su + SM_AHI + (uint32_t)arow * (2 * APAD) + akc * 2;
        aab1 = aab0 + 16 * (2 * APAD);
        int brow0 = wn + (grp >> 1) * 8 + lr;
        int bkc   = (grp & 1) * 8;
        #pragma unroll
        for (int i = 0; i < 4; i++)
            bab[i] = su + SM_BHI + (uint32_t)(brow0 + i * 16) * (2 * APAD) + bkc * 2;
    }

    float acc[2][8][4];
    #pragma unroll
    for (int mt = 0; mt < 2; mt++)
        #pragma unroll
        for (int nt = 0; nt < 8; nt++)
            #pragma unroll
            for (int r = 0; r < 4; r++) acc[mt][nt][r] = 0.f;

    #pragma unroll 1
    for (int pass = 0; pass < 3; pass++) {
        const uint32_t aoff = (pass == 2) ? (SM_ALO - SM_AHI) : 0u;
        const uint32_t boff = (pass == 1) ? (SM_BLO - SM_BHI) : 0u;
        #pragma unroll 2
        for (int ks = 0; ks < 8; ks++) {
            const uint32_t kb = (uint32_t)ks * 32;   // 16 bf16 = 32 bytes
            uint32_t a[2][4], b[4][4];
            LDSM4(a[0][0], a[0][1], a[0][2], a[0][3], aab0 + aoff + kb);
            LDSM4(a[1][0], a[1][1], a[1][2], a[1][3], aab1 + aoff + kb);
            #pragma unroll
            for (int i = 0; i < 4; i++)
                LDSM4(b[i][0], b[i][1], b[i][2], b[i][3], bab[i] + boff + kb);
            // b[i] = {b[2i][0], b[2i][1], b[2i+1][0], b[2i+1][1]}
            #pragma unroll
            for (int mt = 0; mt < 2; mt++)
                #pragma unroll
                for (int nt = 0; nt < 8; nt++) {
                    const int i = nt >> 1, s = (nt & 1) * 2;
                    MMA16816(acc[mt][nt], a[mt], b[i][s], b[i][s + 1]);
                }
        }
    }

    // ---- epilogue: +T4, store, per-column stats (reuse sBhi) ----
    __syncthreads();   // all B reads done
    float* bufS = (float*)(smem + SM_BHI);   // [128][8]
    float* bufQ = bufS + 1024;
    const int w8 = warp & 7;
    #pragma unroll
    for (int nt = 0; nt < 8; nt++) {
        const int c0 = wn + nt * 8 + tg * 2;
        float s0 = 0.f, q0 = 0.f, s1 = 0.f, q1 = 0.f;
        #pragma unroll
        for (int mt = 0; mt < 2; mt++) {
            int rA = wm + mt * 16 + g, rB = rA + 8;
            float2 tA = *(float2*)&sT4[sBi[rA] * 128 + c0];
            float2 tB = *(float2*)&sT4[sBi[rB] * 128 + c0];
            float v0 = acc[mt][nt][0] + tA.x, v1 = acc[mt][nt][1] + tA.y;
            float v2 = acc[mt][nt][2] + tB.x, v3 = acc[mt][nt][3] + tB.y;
            *(float2*)&g_fused[(size_t)(brow + rA) * 128 + c0] = make_float2(v0, v1);
            *(float2*)&g_fused[(size_t)(brow + rB) * 128 + c0] = make_float2(v2, v3);
            s0 += v0 + v2; s1 += v1 + v3;
            q0 += v0 * v0 + v2 * v2; q1 += v1 * v1 + v3 * v3;
        }
        #pragma unroll
        for (int off = 16; off >= 4; off >>= 1) {
            s0 += __shfl_xor_sync(0xffffffffu, s0, off);
            s1 += __shfl_xor_sync(0xffffffffu, s1, off);
            q0 += __shfl_xor_sync(0xffffffffu, q0, off);
            q1 += __shfl_xor_sync(0xffffffffu, q1, off);
        }
        if (g == 0) {
            bufS[c0 * 8 + w8] = s0; bufS[(c0 + 1) * 8 + w8] = s1;
            bufQ[c0 * 8 + w8] = q0; bufQ[(c0 + 1) * 8 + w8] = q1;
        }
    }
    __syncthreads();
    if (tid < 128) {
        float s = 0.f, q = 0.f;
        #pragma unroll
        for (int i = 0; i < 8; i++) { s += bufS[tid * 8 + i]; q += bufQ[tid * 8 + i]; }
        g_partial[tid * GEMM_BLOCKS + blockIdx.x]   = s;
        g_partialsq[tid * GEMM_BLOCKS + blockIdx.x] = q;
    }
}

// =====================================================================
// stats: reduce partials -> BN scale/shift (deterministic)
// =====================================================================
__global__ void stats_kernel(const float* __restrict__ gamma,
                             const float* __restrict__ beta) {
    const int c = blockIdx.x;
    const int tid = threadIdx.x;
    __shared__ float rs[256], rq[256];
    float s = 0.f, q = 0.f;
    for (int b = tid; b < GEMM_BLOCKS; b += 256) {
        s += g_partial[c * GEMM_BLOCKS + b];
        q += g_partialsq[c * GEMM_BLOCKS + b];
    }
    rs[tid] = s; rq[tid] = q;
    __syncthreads();
    for (int o = 128; o > 0; o >>= 1) {
        if (tid < o) { rs[tid] += rs[tid + o]; rq[tid] += rq[tid + o]; }
        __syncthreads();
    }
    if (tid == 0) {
        float mu  = rs[0] / (float)N_PTS;
        float var = rq[0] / (float)N_PTS - mu * mu;
        float sc  = gamma[c] * rsqrtf(var + 1e-5f);
        g_scale[c] = sc;
        g_shift[c] = beta[c] - mu * sc;
    }
}

// =====================================================================
// head2: preds = heads(relu(BN(fused))); also writes the assigned
// output (finalize logic folded in).
// =====================================================================
__global__ void __launch_bounds__(256)
head2_kernel(const int* __restrict__ labels,
             const float* __restrict__ Wb, const float* __restrict__ bb,
             const float* __restrict__ Wc, const float* __restrict__ bc,
             float* __restrict__ out) {
    __shared__ float4 sw[9][32];
    __shared__ float4 ssc[32], ssh[32];
    __shared__ float sb[9];
    __shared__ float skth[NG];
    __shared__ int   slab[NG];
    const int tid = threadIdx.x;
    for (int i = tid; i < 288; i += 256) {
        int j = i >> 5, k4 = i & 31, k = k4 * 4;
        float4 w;
        if (j < 7) w = make_float4(Wb[(k+0)*7+j], Wb[(k+1)*7+j], Wb[(k+2)*7+j], Wb[(k+3)*7+j]);
        else { int jc = j - 7;
               w = make_float4(Wc[(k+0)*2+jc], Wc[(k+1)*2+jc], Wc[(k+2)*2+jc], Wc[(k+3)*2+jc]); }
        sw[j][k4] = w;
    }
    if (tid < 32) { ssc[tid] = ((const float4*)g_scale)[tid]; ssh[tid] = ((const float4*)g_shift)[tid]; }
    if (tid < 9) sb[tid] = (tid < 7) ? bb[tid] : bc[tid - 7];
    if (tid < NG) { skth[tid] = g_kth[tid]; slab[tid] = labels[tid]; }
    __syncthreads();

    const int p = blockIdx.x * 256 + tid;
    float acc[9];
    #pragma unroll
    for (int j = 0; j < 9; j++) acc[j] = sb[j];
    const float4* gf = (const float4*)g_fused;
    #pragma unroll 4
    for (int k4 = 0; k4 < 32; k4++) {
        float4 f = gf[(size_t)p * 32 + k4];
        float4 sc = ssc[k4], sh = ssh[k4];
        float x0 = fmaxf(fmaf(f.x, sc.x, sh.x), 0.f);
        float x1 = fmaxf(fmaf(f.y, sc.y, sh.y), 0.f);
        float x2 = fmaxf(fmaf(f.z, sc.z, sh.z), 0.f);
        float x3 = fmaxf(fmaf(f.w, sc.w, sh.w), 0.f);
        #pragma unroll
        for (int j = 0; j < 9; j++) {
            float4 w = sw[j][k4];
            acc[j] = fmaf(x0, w.x, acc[j]);
            acc[j] = fmaf(x1, w.y, acc[j]);
            acc[j] = fmaf(x2, w.z, acc[j]);
            acc[j] = fmaf(x3, w.w, acc[j]);
        }
    }
    float* o = out + (size_t)p * 9;
    o[0] = acc[0]; o[1] = acc[1]; o[2] = acc[2];
    o[3] = expf(acc[3]); o[4] = expf(acc[4]); o[5] = expf(acc[5]);
    o[6] = acc[6]; o[7] = acc[7]; o[8] = acc[8];

    // finalize: assigned(p) = bi iff level matches and d2 < kth[bi]
    const int lvl = (p < NL0) ? 0 : 1;
    const int bi = g_bi[p];
    const float d2 = g_bd[p];
    int a = (slab[bi] == lvl && d2 < skth[bi]) ? bi : -1;
    out[(size_t)N_PTS * 9 + p] = (float)a;
}

// =====================================================================
// cand: candidates within radius + per-point global argmin (bi, d2).
// Two independent 64-long argmin chains (first-occurrence preserved:
// all indices of chain0 < chain1, ties keep chain0).
// =====================================================================
__global__ void __launch_bounds__(256)
cand_kernel(const float* __restrict__ p0, const float* __restrict__ p1,
            const float* __restrict__ boxes, const int* __restrict__ labels) {
    __shared__ float4 sc0[NG], sc1[NG];
    const int tid = threadIdx.x;
    if (tid < NG) {
        float cx = boxes[tid * 7 + 0], cy = boxes[tid * 7 + 1], cz = boxes[tid * 7 + 2];
        int lvl = labels[tid];
        sc0[tid] = make_float4(cx, cy, cz, (lvl == 0) ? R2_L0 : -1.0f);
        sc1[tid] = make_float4(cx, cy, cz, (lvl == 1) ? R2_L1 : -1.0f);
    }
    __syncthreads();

    const int p = blockIdx.x * 256 + tid;
    float px, py, pz; const float4* Cc;
    if (p < NL0) { px = p0[3 * p]; py = p0[3 * p + 1]; pz = p0[3 * p + 2]; Cc = sc0; }
    else { int q = p - NL0; px = p1[3 * q]; py = p1[3 * q + 1]; pz = p1[3 * q + 2]; Cc = sc1; }

    float bestA = 3.4e38f; int biA = 0;
    float bestB = 3.4e38f; int biB = 64;
    #pragma unroll 4
    for (int g = 0; g < 64; g++) {
        float4 cA = Cc[g];
        float dxA = px - cA.x, dyA = py - cA.y, dzA = pz - cA.z;
        float dA = fmaf(dzA, dzA, fmaf(dyA, dyA, dxA * dxA));
        if (dA < bestA) { bestA = dA; biA = g; }
        if (dA < cA.w) {
            int idx = atomicAdd(&g_cnt[g], 1);
            if (idx < CAND_CAP) g_cand[(size_t)g * CAND_CAP + idx] = dA;
        }
        float4 cB = Cc[g + 64];
        float dxB = px - cB.x, dyB = py - cB.y, dzB = pz - cB.z;
        float dB = fmaf(dzB, dzB, fmaf(dyB, dyB, dxB * dxB));
        if (dB < bestB) { bestB = dB; biB = g + 64; }
        if (dB < cB.w) {
            int idx = atomicAdd(&g_cnt[g + 64], 1);
            if (idx < CAND_CAP) g_cand[(size_t)(g + 64) * CAND_CAP + idx] = dB;
        }
    }
    int bi = (bestB < bestA) ? biB : biA;      // tie -> lower index (chain A)
    float best = (bestB < bestA) ? bestB : bestA;
    g_bi[p] = bi;
    g_bd[p] = best;
}

// =====================================================================
// select: exact 33rd-smallest per gt (candidates; full-scan fallback)
// =====================================================================
#define NBUCK 4096
#define BSCALE 235.0f
#define BCANDMAX 2048
#define KSEL 33

__global__ void __launch_bounds__(512)
select_kernel(const float* __restrict__ p0, const float* __restrict__ p1,
              const float* __restrict__ boxes, const int* __restrict__ labels) {
    const int g = blockIdx.x;
    const int tid = threadIdx.x;
    __shared__ unsigned hist[NBUCK];
    __shared__ unsigned csum[512];
    __shared__ float bcand[BCANDMAX];
    __shared__ int sInfo[3];

    const int lvl = labels[g];
    const float* pts = lvl ? p1 : p0;
    const int n = lvl ? NL1 : NL0;
    const float cx = boxes[g * 7 + 0], cy = boxes[g * 7 + 1], cz = boxes[g * 7 + 2];

    const int cnt = g_cnt[g];
    const bool ok = (cnt >= KSEL && cnt <= CAND_CAP);
    const float* src = &g_cand[(size_t)g * CAND_CAP];
    const int m = ok ? cnt : n;

    for (int i = tid; i < NBUCK; i += 512) hist[i] = 0u;
    if (tid == 0) sInfo[2] = 0;
    __syncthreads();

    for (int i = tid; i < m; i += 512) {
        float d2;
        if (ok) d2 = src[i];
        else {
            float dx = pts[3 * i] - cx, dy = pts[3 * i + 1] - cy, dz = pts[3 * i + 2] - cz;
            d2 = fmaf(dz, dz, fmaf(dy, dy, dx * dx));
        }
        int b = (int)(sqrtf(d2) * BSCALE); b = b > (NBUCK - 1) ? (NBUCK - 1) : b;
        atomicAdd(&hist[b], 1u);
    }
    __syncthreads();

    unsigned cs = 0;
    #pragma unroll
    for (int i = 0; i < 8; i++) cs += hist[tid * 8 + i];
    csum[tid] = cs;
    __syncthreads();
    if (tid == 0) {
        unsigned run = 0; int chunk = 0;
        while (chunk < 512 && run + csum[chunk] < KSEL) { run += csum[chunk]; chunk++; }
        int B = chunk * 8;
        while (run + hist[B] < KSEL) { run += hist[B]; B++; }
        sInfo[0] = B; sInfo[1] = (int)run;
    }
    __syncthreads();
    const int B = sInfo[0];

    for (int i = tid; i < m; i += 512) {
        float d2;
        if (ok) d2 = src[i];
        else {
            float dx = pts[3 * i] - cx, dy = pts[3 * i + 1] - cy, dz = pts[3 * i + 2] - cz;
            d2 = fmaf(dz, dz, fmaf(dy, dy, dx * dx));
        }
        int b = (int)(sqrtf(d2) * BSCALE); b = b > (NBUCK - 1) ? (NBUCK - 1) : b;
        if (b == B) {
            int pos = atomicAdd(&sInfo[2], 1);
            if (pos < BCANDMAX) bcand[pos] = d2;
        }
    }
    __syncthreads();
    if (tid == 0) {
        int mb = sInfo[2]; if (mb > BCANDMAX) mb = BCANDMAX;
        int need = KSEL - sInfo[1];
        float kth = 1e8f;
        for (int r = 0; r < need; r++) {
            float best = 3.4e38f; int bi = 0;
            for (int i = 0; i < mb; i++) { float v = bcand[i]; if (v < best) { best = v; bi = i; } }
            kth = best; bcand[bi] = 3.4e38f;
        }
        g_kth[g] = kth;
    }
}

// =====================================================================
// launch — gemm kept 4th so ncu profiles it
// =====================================================================
extern "C" void kernel_launch(void* const* d_in, const int* in_sizes, int n_in,
                              void* d_out, int out_size) {
    const float* bf    = (const float*)d_in[0];
    const float* text  = (const float*)d_in[1];
    const float* Wf    = (const float*)d_in[2];
    const float* bfu   = (const float*)d_in[3];
    const float* gamma = (const float*)d_in[4];
    const float* beta  = (const float*)d_in[5];
    const float* Wb    = (const float*)d_in[6];
    const float* bb    = (const float*)d_in[7];
    const float* Wc    = (const float*)d_in[8];
    const float* bc    = (const float*)d_in[9];
    const float* p0    = (const float*)d_in[10];
    const float* p1    = (const float*)d_in[11];
    const bool sig = (in_sizes[12] == 128 * 7);
    const float* boxes  = (const float*)d_in[sig ? 12 : 14];
    const int*   bidx   = (const int*)  d_in[sig ? 13 : 12];
    const int*   labels = (const int*)  d_in[sig ? 14 : 13];
    float* out = (float*)d_out;

    cudaFuncSetAttribute(gemm_kernel, cudaFuncAttributeMaxDynamicSharedMemorySize,
                         GEMM_SMEM);

    prep_kernel<<<65, 256>>>(Wf, text, bfu);                        // 1
    cand_kernel<<<N_PTS / 256, 256>>>(p0, p1, boxes, labels);       // 2
    select_kernel<<<NG, 512>>>(p0, p1, boxes, labels);              // 3
    gemm_kernel<<<GEMM_BLOCKS, 512, GEMM_SMEM>>>(bf, bidx);         // 4 <- profiled
    stats_kernel<<<128, 256>>>(gamma, beta);                        // 5
    head2_kernel<<<N_PTS / 256, 256>>>(labels, Wb, bb, Wc, bc, out);// 6
}

// round 16
// speedup vs baseline: 1.7901x; 1.0759x over previous
#include <cuda_runtime.h>
#include <cuda_bf16.h>
#include <math.h>
#include <stdint.h>

// ---------------- problem constants (fixed shapes) ----------------
#define N_PTS    160000
#define NL0      100000
#define NL1       60000
#define NG       128
#define NC       128
#define TILE_ROWS 128
#define N_TILES  (N_PTS / TILE_ROWS)      // 1250
#define NSM      148

// ---------------- device scratch (no allocation allowed) ----------------
__device__ float g_fused[(size_t)N_PTS * NC];           // X @ W + T4[bidx]
__device__ float g_T4[4 * NC];
__device__ __align__(16) __nv_bfloat16 g_Whi[NC * NC];  // [n][k] = bf16(W[k][n])
__device__ __align__(16) __nv_bfloat16 g_Wlo[NC * NC];  // residual
__device__ float g_partial[NC * NSM];
__device__ float g_partialsq[NC * NSM];
__device__ __align__(16) float g_scale[NC];
__device__ __align__(16) float g_shift[NC];
__device__ float g_kth[NG];
__device__ int   g_bi[N_PTS];                           // per-point global argmin
__device__ float g_bd[N_PTS];                           // its d2

#define CAND_CAP 2048
__device__ float g_cand[(size_t)NG * CAND_CAP];
__device__ int   g_cnt[NG];

#define R2_L0 1.44f
#define R2_L1 2.25f

// ---------------- mma.sync / ldmatrix (baseline PTX, sm_103-safe) ----
#define MMA16816(d, a, b0, b1) \
    asm volatile("mma.sync.aligned.m16n8k16.row.col.f32.bf16.bf16.f32 " \
        "{%0,%1,%2,%3}, {%4,%5,%6,%7}, {%8,%9}, {%0,%1,%2,%3};" \
        : "+f"((d)[0]), "+f"((d)[1]), "+f"((d)[2]), "+f"((d)[3]) \
        : "r"((a)[0]), "r"((a)[1]), "r"((a)[2]), "r"((a)[3]), \
          "r"(b0), "r"(b1))

#define LDSM4(r0, r1, r2, r3, addr) \
    asm volatile("ldmatrix.sync.aligned.m8n8.x4.shared.b16 {%0,%1,%2,%3}, [%4];" \
        : "=r"(r0), "=r"(r1), "=r"(r2), "=r"(r3) : "r"(addr))

#define CVT_BF16X2(res, a, b) \
    asm("cvt.rn.bf16x2.f32 %0, %1, %2;" : "=r"(res) : "f"(b), "f"(a))

__device__ __forceinline__ void split2(float a, float b, uint32_t& hp, uint32_t& lp) {
    CVT_BF16X2(hp, a, b);
    float ha = __uint_as_float(hp << 16);
    float hb = __uint_as_float(hp & 0xffff0000u);
    float ra = a - ha, rb = b - hb;
    CVT_BF16X2(lp, ra, rb);
}

__device__ __forceinline__ uint32_t smem_u32(const void* p) {
    uint32_t a;
    asm("{ .reg .u64 t; cvta.to.shared.u64 t, %1; cvt.u32.u64 %0, t; }"
        : "=r"(a) : "l"(p));
    return a;
}

// gemm smem layout: padded rows of 136 bf16 (272 B)
#define APAD 136
#define SM_BHI 0
#define SM_BLO (SM_BHI + 128 * APAD * 2)      // 34816
#define SM_AHI (SM_BLO + 128 * APAD * 2)      // 69632
#define SM_ALO (SM_AHI + 128 * APAD * 2)      // 104448
#define SM_T4  (SM_ALO + 128 * APAD * 2)      // 139264, float[512]
#define SM_BIDX (SM_T4 + 2048)                // 141312, int[128]
#define SM_STAT (SM_BIDX + 512)               // 141824, float[2048]
#define GEMM_SMEM (SM_STAT + 8192)            // 150016 (~146.5 KB)

// =====================================================================
// prep: blocks 0..63 = W split; block 64 = T4 + zero cnt
// =====================================================================
__global__ void prep_kernel(const float* __restrict__ Wf,
                            const float* __restrict__ text,
                            const float* __restrict__ bfuse) {
    const int tid = threadIdx.x;
    if (blockIdx.x < 64) {
        int i = blockIdx.x * 256 + tid;       // 16384
        int n = i >> 7, k = i & 127;
        float v = Wf[k * 128 + n];
        __nv_bfloat16 h = __float2bfloat16(v);
        float r = v - __bfloat162float(h);
        g_Whi[n * 128 + k] = h;
        g_Wlo[n * 128 + k] = __float2bfloat16(r);
    } else {
        if (tid < NG) g_cnt[tid] = 0;
        for (int u = tid; u < 512; u += 256) {
            int t = u >> 7, c = u & 127;
            float acc = bfuse[c];
            #pragma unroll 8
            for (int k = 0; k < 128; k++)
                acc = fmaf(text[t * 128 + k], Wf[(128 + k) * 128 + c], acc);
            g_T4[u] = acc;
        }
    }
}

// =====================================================================
// Persistent GEMM: g_fused = X @ W + T4[bidx]; BN partials per SM.
// grid=148, 512 threads, 128-row tiles; register prefetch of next tile
// overlaps DRAM with the tensor mainloop. B/T4 loaded once per CTA.
// 16 warps: 8 row-strips x 2 col-strips, warp tile 16x64.
// =====================================================================
__global__ void __launch_bounds__(512, 1)
gemm_kernel(const float* __restrict__ bf, const int* __restrict__ bidx) {
    extern __shared__ char smem[];
    __nv_bfloat16* sBhi = (__nv_bfloat16*)(smem + SM_BHI);
    __nv_bfloat16* sBlo = (__nv_bfloat16*)(smem + SM_BLO);
    __nv_bfloat16* sAhi = (__nv_bfloat16*)(smem + SM_AHI);
    __nv_bfloat16* sAlo = (__nv_bfloat16*)(smem + SM_ALO);
    float* sT4  = (float*)(smem + SM_T4);
    int*   sBi  = (int*)(smem + SM_BIDX);
    float* bufS = (float*)(smem + SM_STAT);   // [128][8]
    float* bufQ = bufS + 1024;

    const int tid  = threadIdx.x;
    const int warp = tid >> 5;
    const int lane = tid & 31;
    const int g  = lane >> 2;          // 0..7
    const int tg = lane & 3;           // 0..3
    const int bid = blockIdx.x;

    // ---- one-time: B (W^T hi/lo), T4, stat zero ----
    if (tid < 256) {
        int n = tid & 127;
        const uint4* src = (const uint4*)((tid < 128 ? g_Whi : g_Wlo) + n * 128);
        __nv_bfloat16* dst = (tid < 128 ? sBhi : sBlo) + n * APAD;
        #pragma unroll
        for (int j = 0; j < 16; j++)
            *(uint4*)(dst + j * 8) = src[j];
    }
    sT4[tid] = g_T4[tid];
    #pragma unroll
    for (int i = 0; i < 4; i++) bufS[tid + i * 512] = 0.f;   // zeros bufS+bufQ

    const int wm = (warp & 7) * 16;    // row strip
    const int wn = (warp >> 3) * 64;   // col strip
    const int grp = lane >> 3, lr = lane & 7;
    const uint32_t su = smem_u32(smem);
    uint32_t aab, bab[4];
    {
        int arow = wm + (grp & 1) * 8 + lr;
        int akc  = (grp >> 1) * 8;
        aab = su + SM_AHI + (uint32_t)arow * (2 * APAD) + akc * 2;
        int brow0 = wn + (grp >> 1) * 8 + lr;
        int bkc   = (grp & 1) * 8;
        #pragma unroll
        for (int i = 0; i < 4; i++)
            bab[i] = su + SM_BHI + (uint32_t)(brow0 + i * 16) * (2 * APAD) + bkc * 2;
    }
    const int w8 = warp & 7;

    // ---- prefetch first tile into registers ----
    const float4* bf4 = (const float4*)bf;
    float4 pf[8];
    int bidreg = 0;
    {
        const size_t base = (size_t)bid * TILE_ROWS * 32;
        #pragma unroll
        for (int it = 0; it < 8; it++) {
            int idx = it * 512 + tid;           // 4096 float4 per tile
            pf[it] = bf4[base + idx];
        }
        if (tid < 128) bidreg = bidx[bid * TILE_ROWS + tid];
    }

    for (int t = bid; t < N_TILES; t += NSM) {
        const int brow = t * TILE_ROWS;
        __syncthreads();   // prior mainloop/epilogue done before overwriting sA/sBi

        // ---- convert prefetched regs -> smem ----
        #pragma unroll
        for (int it = 0; it < 8; it++) {
            int idx = it * 512 + tid;
            int r = idx >> 5, c4 = idx & 31;
            float4 v = pf[it];
            uint32_t h0, l0, h1, l1;
            split2(v.x, v.y, h0, l0);
            split2(v.z, v.w, h1, l1);
            *(uint2*)(sAhi + r * APAD + c4 * 4) = make_uint2(h0, h1);
            *(uint2*)(sAlo + r * APAD + c4 * 4) = make_uint2(l0, l1);
        }
        if (tid < 128) sBi[tid] = bidreg;
        __syncthreads();

        // ---- prefetch next tile (hidden under mainloop) ----
        const int tn = t + NSM;
        if (tn < N_TILES) {
            const size_t base = (size_t)tn * TILE_ROWS * 32;
            #pragma unroll
            for (int it = 0; it < 8; it++) {
                int idx = it * 512 + tid;
                pf[it] = bf4[base + idx];
            }
            if (tid < 128) bidreg = bidx[tn * TILE_ROWS + tid];
        }

        // ---- mainloop: 3 passes x 8 ks ----
        float acc[8][4];
        #pragma unroll
        for (int nt = 0; nt < 8; nt++)
            #pragma unroll
            for (int r = 0; r < 4; r++) acc[nt][r] = 0.f;

        #pragma unroll 1
        for (int pass = 0; pass < 3; pass++) {
            const uint32_t aoff = (pass == 2) ? (uint32_t)(SM_ALO - SM_AHI) : 0u;
            const uint32_t boff = (pass == 1) ? (uint32_t)(SM_BLO - SM_BHI) : 0u;
            #pragma unroll 2
            for (int ks = 0; ks < 8; ks++) {
                const uint32_t kb = (uint32_t)ks * 32;
                uint32_t a[4], b[4][4];
                LDSM4(a[0], a[1], a[2], a[3], aab + aoff + kb);
                #pragma unroll
                for (int i = 0; i < 4; i++)
                    LDSM4(b[i][0], b[i][1], b[i][2], b[i][3], bab[i] + boff + kb);
                #pragma unroll
                for (int nt = 0; nt < 8; nt++) {
                    const int i = nt >> 1, s = (nt & 1) * 2;
                    MMA16816(acc[nt], a, b[i][s], b[i][s + 1]);
                }
            }
        }

        // ---- epilogue: +T4, store, accumulate stats ----
        #pragma unroll
        for (int nt = 0; nt < 8; nt++) {
            const int c0 = wn + nt * 8 + tg * 2;
            int rA = wm + g, rB = rA + 8;
            float2 tA = *(float2*)&sT4[sBi[rA] * 128 + c0];
            float2 tB = *(float2*)&sT4[sBi[rB] * 128 + c0];
            float v0 = acc[nt][0] + tA.x, v1 = acc[nt][1] + tA.y;
            float v2 = acc[nt][2] + tB.x, v3 = acc[nt][3] + tB.y;
            *(float2*)&g_fused[(size_t)(brow + rA) * 128 + c0] = make_float2(v0, v1);
            *(float2*)&g_fused[(size_t)(brow + rB) * 128 + c0] = make_float2(v2, v3);
            float s0 = v0 + v2, s1 = v1 + v3;
            float q0 = v0 * v0 + v2 * v2, q1 = v1 * v1 + v3 * v3;
            #pragma unroll
            for (int off = 16; off >= 4; off >>= 1) {
                s0 += __shfl_xor_sync(0xffffffffu, s0, off);
                s1 += __shfl_xor_sync(0xffffffffu, s1, off);
                q0 += __shfl_xor_sync(0xffffffffu, q0, off);
                q1 += __shfl_xor_sync(0xffffffffu, q1, off);
            }
            if (g == 0) {   // slot (c0,w8) owned by this thread every tile
                bufS[c0 * 8 + w8] += s0; bufS[(c0 + 1) * 8 + w8] += s1;
                bufQ[c0 * 8 + w8] += q0; bufQ[(c0 + 1) * 8 + w8] += q1;
            }
        }
    }

    __syncthreads();
    if (tid < 128) {
        float s = 0.f, q = 0.f;
        #pragma unroll
        for (int i = 0; i < 8; i++) { s += bufS[tid * 8 + i]; q += bufQ[tid * 8 + i]; }
        g_partial[tid * NSM + bid]   = s;
        g_partialsq[tid * NSM + bid] = q;
    }
}

// =====================================================================
// stats: reduce 148 partials -> BN scale/shift (deterministic)
// =====================================================================
__global__ void stats_kernel(const float* __restrict__ gamma,
                             const float* __restrict__ beta) {
    const int c = blockIdx.x;
    const int tid = threadIdx.x;
    __shared__ float rs[256], rq[256];
    float s = 0.f, q = 0.f;
    if (tid < NSM) {
        s = g_partial[c * NSM + tid];
        q = g_partialsq[c * NSM + tid];
    }
    rs[tid] = s; rq[tid] = q;
    __syncthreads();
    for (int o = 128; o > 0; o >>= 1) {
        if (tid < o) { rs[tid] += rs[tid + o]; rq[tid] += rq[tid + o]; }
        __syncthreads();
    }
    if (tid == 0) {
        float mu  = rs[0] / (float)N_PTS;
        float var = rq[0] / (float)N_PTS - mu * mu;
        float sc  = gamma[c] * rsqrtf(var + 1e-5f);
        g_scale[c] = sc;
        g_shift[c] = beta[c] - mu * sc;
    }
}

// =====================================================================
// head2: preds = heads(relu(BN(fused))); finalize folded in.
// =====================================================================
__global__ void __launch_bounds__(256)
head2_kernel(const int* __restrict__ labels,
             const float* __restrict__ Wb, const float* __restrict__ bb,
             const float* __restrict__ Wc, const float* __restrict__ bc,
             float* __restrict__ out) {
    __shared__ float4 sw[9][32];
    __shared__ float4 ssc[32], ssh[32];
    __shared__ float sb[9];
    __shared__ float skth[NG];
    __shared__ int   slab[NG];
    const int tid = threadIdx.x;
    for (int i = tid; i < 288; i += 256) {
        int j = i >> 5, k4 = i & 31, k = k4 * 4;
        float4 w;
        if (j < 7) w = make_float4(Wb[(k+0)*7+j], Wb[(k+1)*7+j], Wb[(k+2)*7+j], Wb[(k+3)*7+j]);
        else { int jc = j - 7;
               w = make_float4(Wc[(k+0)*2+jc], Wc[(k+1)*2+jc], Wc[(k+2)*2+jc], Wc[(k+3)*2+jc]); }
        sw[j][k4] = w;
    }
    if (tid < 32) { ssc[tid] = ((const float4*)g_scale)[tid]; ssh[tid] = ((const float4*)g_shift)[tid]; }
    if (tid < 9) sb[tid] = (tid < 7) ? bb[tid] : bc[tid - 7];
    if (tid < NG) { skth[tid] = g_kth[tid]; slab[tid] = labels[tid]; }
    __syncthreads();

    const int p = blockIdx.x * 256 + tid;
    float acc[9];
    #pragma unroll
    for (int j = 0; j < 9; j++) acc[j] = sb[j];
    const float4* gf = (const float4*)g_fused;
    #pragma unroll 4
    for (int k4 = 0; k4 < 32; k4++) {
        float4 f = gf[(size_t)p * 32 + k4];
        float4 sc = ssc[k4], sh = ssh[k4];
        float x0 = fmaxf(fmaf(f.x, sc.x, sh.x), 0.f);
        float x1 = fmaxf(fmaf(f.y, sc.y, sh.y), 0.f);
        float x2 = fmaxf(fmaf(f.z, sc.z, sh.z), 0.f);
        float x3 = fmaxf(fmaf(f.w, sc.w, sh.w), 0.f);
        #pragma unroll
        for (int j = 0; j < 9; j++) {
            float4 w = sw[j][k4];
            acc[j] = fmaf(x0, w.x, acc[j]);
            acc[j] = fmaf(x1, w.y, acc[j]);
            acc[j] = fmaf(x2, w.z, acc[j]);
            acc[j] = fmaf(x3, w.w, acc[j]);
        }
    }
    float* o = out + (size_t)p * 9;
    o[0] = acc[0]; o[1] = acc[1]; o[2] = acc[2];
    o[3] = expf(acc[3]); o[4] = expf(acc[4]); o[5] = expf(acc[5]);
    o[6] = acc[6]; o[7] = acc[7]; o[8] = acc[8];

    const int lvl = (p < NL0) ? 0 : 1;
    const int bi = g_bi[p];
    const float d2 = g_bd[p];
    int a = (slab[bi] == lvl && d2 < skth[bi]) ? bi : -1;
    out[(size_t)N_PTS * 9 + p] = (float)a;
}

// =====================================================================
// cand: candidates within radius + per-point global argmin (bi, d2).
// =====================================================================
__global__ void __launch_bounds__(256)
cand_kernel(const float* __restrict__ p0, const float* __restrict__ p1,
            const float* __restrict__ boxes, const int* __restrict__ labels) {
    __shared__ float4 sc0[NG], sc1[NG];
    const int tid = threadIdx.x;
    if (tid < NG) {
        float cx = boxes[tid * 7 + 0], cy = boxes[tid * 7 + 1], cz = boxes[tid * 7 + 2];
        int lvl = labels[tid];
        sc0[tid] = make_float4(cx, cy, cz, (lvl == 0) ? R2_L0 : -1.0f);
        sc1[tid] = make_float4(cx, cy, cz, (lvl == 1) ? R2_L1 : -1.0f);
    }
    __syncthreads();

    const int p = blockIdx.x * 256 + tid;
    float px, py, pz; const float4* Cc;
    if (p < NL0) { px = p0[3 * p]; py = p0[3 * p + 1]; pz = p0[3 * p + 2]; Cc = sc0; }
    else { int q = p - NL0; px = p1[3 * q]; py = p1[3 * q + 1]; pz = p1[3 * q + 2]; Cc = sc1; }

    float bestA = 3.4e38f; int biA = 0;
    float bestB = 3.4e38f; int biB = 64;
    #pragma unroll 4
    for (int g = 0; g < 64; g++) {
        float4 cA = Cc[g];
        float dxA = px - cA.x, dyA = py - cA.y, dzA = pz - cA.z;
        float dA = fmaf(dzA, dzA, fmaf(dyA, dyA, dxA * dxA));
        if (dA < bestA) { bestA = dA; biA = g; }
        if (dA < cA.w) {
            int idx = atomicAdd(&g_cnt[g], 1);
            if (idx < CAND_CAP) g_cand[(size_t)g * CAND_CAP + idx] = dA;
        }
        float4 cB = Cc[g + 64];
        float dxB = px - cB.x, dyB = py - cB.y, dzB = pz - cB.z;
        float dB = fmaf(dzB, dzB, fmaf(dyB, dyB, dxB * dxB));
        if (dB < bestB) { bestB = dB; biB = g + 64; }
        if (dB < cB.w) {
            int idx = atomicAdd(&g_cnt[g + 64], 1);
            if (idx < CAND_CAP) g_cand[(size_t)(g + 64) * CAND_CAP + idx] = dB;
        }
    }
    int bi = (bestB < bestA) ? biB : biA;
    float best = (bestB < bestA) ? bestB : bestA;
    g_bi[p] = bi;
    g_bd[p] = best;
}

// =====================================================================
// select: exact 33rd-smallest per gt (candidates; full-scan fallback)
// =====================================================================
#define NBUCK 4096
#define BSCALE 235.0f
#define BCANDMAX 2048
#define KSEL 33

__global__ void __launch_bounds__(512)
select_kernel(const float* __restrict__ p0, const float* __restrict__ p1,
              const float* __restrict__ boxes, const int* __restrict__ labels) {
    const int g = blockIdx.x;
    const int tid = threadIdx.x;
    __shared__ unsigned hist[NBUCK];
    __shared__ unsigned csum[512];
    __shared__ float bcand[BCANDMAX];
    __shared__ int sInfo[3];

    const int lvl = labels[g];
    const float* pts = lvl ? p1 : p0;
    const int n = lvl ? NL1 : NL0;
    const float cx = boxes[g * 7 + 0], cy = boxes[g * 7 + 1], cz = boxes[g * 7 + 2];

    const int cnt = g_cnt[g];
    const bool ok = (cnt >= KSEL && cnt <= CAND_CAP);
    const float* src = &g_cand[(size_t)g * CAND_CAP];
    const int m = ok ? cnt : n;

    for (int i = tid; i < NBUCK; i += 512) hist[i] = 0u;
    if (tid == 0) sInfo[2] = 0;
    __syncthreads();

    for (int i = tid; i < m; i += 512) {
        float d2;
        if (ok) d2 = src[i];
        else {
            float dx = pts[3 * i] - cx, dy = pts[3 * i + 1] - cy, dz = pts[3 * i + 2] - cz;
            d2 = fmaf(dz, dz, fmaf(dy, dy, dx * dx));
        }
        int b = (int)(sqrtf(d2) * BSCALE); b = b > (NBUCK - 1) ? (NBUCK - 1) : b;
        atomicAdd(&hist[b], 1u);
    }
    __syncthreads();

    unsigned cs = 0;
    #pragma unroll
    for (int i = 0; i < 8; i++) cs += hist[tid * 8 + i];
    csum[tid] = cs;
    __syncthreads();
    if (tid == 0) {
        unsigned run = 0; int chunk = 0;
        while (chunk < 512 && run + csum[chunk] < KSEL) { run += csum[chunk]; chunk++; }
        int B = chunk * 8;
        while (run + hist[B] < KSEL) { run += hist[B]; B++; }
        sInfo[0] = B; sInfo[1] = (int)run;
    }
    __syncthreads();
    const int B = sInfo[0];

    for (int i = tid; i < m; i += 512) {
        float d2;
        if (ok) d2 = src[i];
        else {
            float dx = pts[3 * i] - cx, dy = pts[3 * i + 1] - cy, dz = pts[3 * i + 2] - cz;
            d2 = fmaf(dz, dz, fmaf(dy, dy, dx * dx));
        }
        int b = (int)(sqrtf(d2) * BSCALE); b = b > (NBUCK - 1) ? (NBUCK - 1) : b;
        if (b == B) {
            int pos = atomicAdd(&sInfo[2], 1);
            if (pos < BCANDMAX) bcand[pos] = d2;
        }
    }
    __syncthreads();
    if (tid == 0) {
        int mb = sInfo[2]; if (mb > BCANDMAX) mb = BCANDMAX;
        int need = KSEL - sInfo[1];
        float kth = 1e8f;
        for (int r = 0; r < need; r++) {
            float best = 3.4e38f; int bi = 0;
            for (int i = 0; i < mb; i++) { float v = bcand[i]; if (v < best) { best = v; bi = i; } }
            kth = best; bcand[bi] = 3.4e38f;
        }
        g_kth[g] = kth;
    }
}

// =====================================================================
// launch — gemm kept 4th so ncu profiles it
// =====================================================================
extern "C" void kernel_launch(void* const* d_in, const int* in_sizes, int n_in,
                              void* d_out, int out_size) {
    const float* bf    = (const float*)d_in[0];
    const float* text  = (const float*)d_in[1];
    const float* Wf    = (const float*)d_in[2];
    const float* bfu   = (const float*)d_in[3];
    const float* gamma = (const float*)d_in[4];
    const float* beta  = (const float*)d_in[5];
    const float* Wb    = (const float*)d_in[6];
    const float* bb    = (const float*)d_in[7];
    const float* Wc    = (const float*)d_in[8];
    const float* bc    = (const float*)d_in[9];
    const float* p0    = (const float*)d_in[10];
    const float* p1    = (const float*)d_in[11];
    const bool sig = (in_sizes[12] == 128 * 7);
    const float* boxes  = (const float*)d_in[sig ? 12 : 14];
    const int*   bidx   = (const int*)  d_in[sig ? 13 : 12];
    const int*   labels = (const int*)  d_in[sig ? 14 : 13];
    float* out = (float*)d_out;

    cudaFuncSetAttribute(gemm_kernel, cudaFuncAttributeMaxDynamicSharedMemorySize,
                         GEMM_SMEM);

    prep_kernel<<<65, 256>>>(Wf, text, bfu);                        // 1
    cand_kernel<<<N_PTS / 256, 256>>>(p0, p1, boxes, labels);       // 2
    select_kernel<<<NG, 512>>>(p0, p1, boxes, labels);              // 3
    gemm_kernel<<<NSM, 512, GEMM_SMEM>>>(bf, bidx);                 // 4 <- profiled
    stats_kernel<<<128, 256>>>(gamma, beta);                        // 5
    head2_kernel<<<N_PTS / 256, 256>>>(labels, Wb, bb, Wc, bc, out);// 6
}

// round 17
// speedup vs baseline: 2.0078x; 1.1216x over previous
#include <cuda_runtime.h>
#include <cuda_bf16.h>
#include <math.h>
#include <stdint.h>

// ---------------- problem constants (fixed shapes) ----------------
#define N_PTS    160000
#define NL0      100000
#define NL1       60000
#define NG       128
#define NC       128
#define TILE_ROWS 128
#define N_TILES  (N_PTS / TILE_ROWS)      // 1250
#define NSM      148

// ---------------- device scratch (no allocation allowed) ----------------
__device__ float g_fused[(size_t)N_PTS * NC];           // X @ W + T4[bidx]
__device__ float g_T4[4 * NC];
__device__ __align__(16) __nv_bfloat16 g_Whi[NC * NC];  // [n][k] = bf16(W[k][n])
__device__ __align__(16) __nv_bfloat16 g_Wlo[NC * NC];  // residual
__device__ float g_partial[NC * NSM];
__device__ float g_partialsq[NC * NSM];
__device__ __align__(16) float g_scale[NC];
__device__ __align__(16) float g_shift[NC];
__device__ float g_kth[NG];
__device__ int   g_bi[N_PTS];                           // per-point global argmin
__device__ float g_bd[N_PTS];                           // its d2

#define CAND_CAP 2048
__device__ float g_cand[(size_t)NG * CAND_CAP];
__device__ int   g_cnt[NG];

#define R2_L0 1.44f
#define R2_L1 2.25f

// ---------------- mma.sync / ldmatrix (baseline PTX, sm_103-safe) ----
#define MMA16816(d, a, b0, b1) \
    asm volatile("mma.sync.aligned.m16n8k16.row.col.f32.bf16.bf16.f32 " \
        "{%0,%1,%2,%3}, {%4,%5,%6,%7}, {%8,%9}, {%0,%1,%2,%3};" \
        : "+f"((d)[0]), "+f"((d)[1]), "+f"((d)[2]), "+f"((d)[3]) \
        : "r"((a)[0]), "r"((a)[1]), "r"((a)[2]), "r"((a)[3]), \
          "r"(b0), "r"(b1))

#define LDSM4(r0, r1, r2, r3, addr) \
    asm volatile("ldmatrix.sync.aligned.m8n8.x4.shared.b16 {%0,%1,%2,%3}, [%4];" \
        : "=r"(r0), "=r"(r1), "=r"(r2), "=r"(r3) : "r"(addr))

#define CVT_BF16X2(res, a, b) \
    asm("cvt.rn.bf16x2.f32 %0, %1, %2;" : "=r"(res) : "f"(b), "f"(a))

__device__ __forceinline__ void split2(float a, float b, uint32_t& hp, uint32_t& lp) {
    CVT_BF16X2(hp, a, b);
    float ha = __uint_as_float(hp << 16);
    float hb = __uint_as_float(hp & 0xffff0000u);
    float ra = a - ha, rb = b - hb;
    CVT_BF16X2(lp, ra, rb);
}

__device__ __forceinline__ uint32_t smem_u32(const void* p) {
    uint32_t a;
    asm("{ .reg .u64 t; cvta.to.shared.u64 t, %1; cvt.u32.u64 %0, t; }"
        : "=r"(a) : "l"(p));
    return a;
}

// gemm smem layout: padded rows of 136 bf16 (272 B)
#define APAD 136
#define SM_BHI 0
#define SM_BLO (SM_BHI + 128 * APAD * 2)      // 34816
#define SM_AHI (SM_BLO + 128 * APAD * 2)      // 69632
#define SM_ALO (SM_AHI + 128 * APAD * 2)      // 104448
#define SM_T4  (SM_ALO + 128 * APAD * 2)      // 139264, float[512]
#define SM_BIDX (SM_T4 + 2048)                // 141312, int[128]
#define SM_STAT (SM_BIDX + 512)               // 141824, float[2048]*2
#define GEMM_SMEM (SM_STAT + 16384)           // 158208 (~154.5 KB)
// sOut (output staging, 128 x 136 f32 = 69632 B) aliases sAhi+sAlo.
#define OPAD 136

// =====================================================================
// prep: blocks 0..63 = W split; block 64 = T4 + zero cnt
// =====================================================================
__global__ void prep_kernel(const float* __restrict__ Wf,
                            const float* __restrict__ text,
                            const float* __restrict__ bfuse) {
    const int tid = threadIdx.x;
    if (blockIdx.x < 64) {
        int i = blockIdx.x * 256 + tid;       // 16384
        int n = i >> 7, k = i & 127;
        float v = Wf[k * 128 + n];
        __nv_bfloat16 h = __float2bfloat16(v);
        float r = v - __bfloat162float(h);
        g_Whi[n * 128 + k] = h;
        g_Wlo[n * 128 + k] = __float2bfloat16(r);
    } else {
        if (tid < NG) g_cnt[tid] = 0;
        for (int u = tid; u < 512; u += 256) {
            int t = u >> 7, c = u & 127;
            float acc = bfuse[c];
            #pragma unroll 8
            for (int k = 0; k < 128; k++)
                acc = fmaf(text[t * 128 + k], Wf[(128 + k) * 128 + c], acc);
            g_T4[u] = acc;
        }
    }
}

// =====================================================================
// Persistent GEMM: g_fused = X @ W + T4[bidx]; BN partials per SM.
// grid=148, 512 threads, 128-row tiles; register prefetch; 16 warps in
// 4x4 strips (warp tile 32x32) to minimize LDSM traffic; epilogue
// staged through smem for coalesced stores + register BN stats.
// =====================================================================
__global__ void __launch_bounds__(512, 1)
gemm_kernel(const float* __restrict__ bf, const int* __restrict__ bidx) {
    extern __shared__ char smem[];
    __nv_bfloat16* sBhi = (__nv_bfloat16*)(smem + SM_BHI);
    __nv_bfloat16* sBlo = (__nv_bfloat16*)(smem + SM_BLO);
    __nv_bfloat16* sAhi = (__nv_bfloat16*)(smem + SM_AHI);
    __nv_bfloat16* sAlo = (__nv_bfloat16*)(smem + SM_ALO);
    float* sOut = (float*)(smem + SM_AHI);    // aliases sA (post-mainloop)
    float* sT4  = (float*)(smem + SM_T4);
    int*   sBi  = (int*)(smem + SM_BIDX);
    float* bufS = (float*)(smem + SM_STAT);   // [128][16]
    float* bufQ = bufS + 2048;

    const int tid  = threadIdx.x;
    const int warp = tid >> 5;
    const int lane = tid & 31;
    const int g  = lane >> 2;          // 0..7
    const int tg = lane & 3;           // 0..3
    const int bid = blockIdx.x;

    // ---- one-time: B (W^T hi/lo), T4 ----
    if (tid < 256) {
        int n = tid & 127;
        const uint4* src = (const uint4*)((tid < 128 ? g_Whi : g_Wlo) + n * 128);
        __nv_bfloat16* dst = (tid < 128 ? sBhi : sBlo) + n * APAD;
        #pragma unroll
        for (int j = 0; j < 16; j++)
            *(uint4*)(dst + j * 8) = src[j];
    }
    sT4[tid] = g_T4[tid];

    const int wm = (warp & 3) * 32;    // row strip (4 strips)
    const int wn = (warp >> 2) * 32;   // col strip (4 strips)
    const int grp = lane >> 3, lr = lane & 7;
    const uint32_t su = smem_u32(smem);
    uint32_t aab0, aab1, bab[2];
    {
        int arow = wm + (grp & 1) * 8 + lr;
        int akc  = (grp >> 1) * 8;
        aab0 = su + SM_AHI + (uint32_t)arow * (2 * APAD) + akc * 2;
        aab1 = aab0 + 16 * (2 * APAD);
        int brow0 = wn + (grp >> 1) * 8 + lr;
        int bkc   = (grp & 1) * 8;
        #pragma unroll
        for (int i = 0; i < 2; i++)
            bab[i] = su + SM_BHI + (uint32_t)(brow0 + i * 16) * (2 * APAD) + bkc * 2;
    }

    // per-thread stats accumulators (cols cbase..cbase+3, row-class w)
    const int cbase = (tid & 31) * 4;
    const int wrow  = tid >> 5;
    float sacc[4] = {0.f, 0.f, 0.f, 0.f}, qacc[4] = {0.f, 0.f, 0.f, 0.f};

    // ---- prefetch first tile into registers ----
    const float4* bf4 = (const float4*)bf;
    float4 pf[8];
    int bidreg = 0;
    {
        const size_t base = (size_t)bid * TILE_ROWS * 32;
        #pragma unroll
        for (int it = 0; it < 8; it++)
            pf[it] = bf4[base + it * 512 + tid];
        if (tid < 128) bidreg = bidx[bid * TILE_ROWS + tid];
    }

    for (int t = bid; t < N_TILES; t += NSM) {
        const int brow = t * TILE_ROWS;
        __syncthreads();   // staged-store reads of sOut done; safe to overwrite sA

        // ---- convert prefetched regs -> smem ----
        #pragma unroll
        for (int it = 0; it < 8; it++) {
            int idx = it * 512 + tid;
            int r = idx >> 5, c4 = idx & 31;
            float4 v = pf[it];
            uint32_t h0, l0, h1, l1;
            split2(v.x, v.y, h0, l0);
            split2(v.z, v.w, h1, l1);
            *(uint2*)(sAhi + r * APAD + c4 * 4) = make_uint2(h0, h1);
            *(uint2*)(sAlo + r * APAD + c4 * 4) = make_uint2(l0, l1);
        }
        if (tid < 128) sBi[tid] = bidreg;
        __syncthreads();

        // ---- prefetch next tile (hidden under mainloop) ----
        const int tn = t + NSM;
        if (tn < N_TILES) {
            const size_t base = (size_t)tn * TILE_ROWS * 32;
            #pragma unroll
            for (int it = 0; it < 8; it++)
                pf[it] = bf4[base + it * 512 + tid];
            if (tid < 128) bidreg = bidx[tn * TILE_ROWS + tid];
        }

        // ---- mainloop: 3 passes x 8 ks, warp tile 32x32 ----
        float acc[2][4][4];
        #pragma unroll
        for (int mt = 0; mt < 2; mt++)
            #pragma unroll
            for (int nt = 0; nt < 4; nt++)
                #pragma unroll
                for (int r = 0; r < 4; r++) acc[mt][nt][r] = 0.f;

        #pragma unroll 1
        for (int pass = 0; pass < 3; pass++) {
            const uint32_t aoff = (pass == 2) ? (uint32_t)(SM_ALO - SM_AHI) : 0u;
            const uint32_t boff = (pass == 1) ? (uint32_t)(SM_BLO - SM_BHI) : 0u;
            #pragma unroll 2
            for (int ks = 0; ks < 8; ks++) {
                const uint32_t kb = (uint32_t)ks * 32;
                uint32_t a[2][4], b[2][4];
                LDSM4(a[0][0], a[0][1], a[0][2], a[0][3], aab0 + aoff + kb);
                LDSM4(a[1][0], a[1][1], a[1][2], a[1][3], aab1 + aoff + kb);
                #pragma unroll
                for (int i = 0; i < 2; i++)
                    LDSM4(b[i][0], b[i][1], b[i][2], b[i][3], bab[i] + boff + kb);
                #pragma unroll
                for (int mt = 0; mt < 2; mt++)
                    #pragma unroll
                    for (int nt = 0; nt < 4; nt++) {
                        const int i = nt >> 1, s = (nt & 1) * 2;
                        MMA16816(acc[mt][nt], a[mt], b[i][s], b[i][s + 1]);
                    }
            }
        }

        // ---- epilogue: +T4, stage into sOut (aliases sA) ----
        __syncthreads();   // all mainloop sA reads done
        #pragma unroll
        for (int mt = 0; mt < 2; mt++) {
            #pragma unroll
            for (int nt = 0; nt < 4; nt++) {
                const int c0 = wn + nt * 8 + tg * 2;
                int rA = wm + mt * 16 + g, rB = rA + 8;
                float2 tA = *(float2*)&sT4[sBi[rA] * 128 + c0];
                float2 tB = *(float2*)&sT4[sBi[rB] * 128 + c0];
                *(float2*)&sOut[rA * OPAD + c0] =
                    make_float2(acc[mt][nt][0] + tA.x, acc[mt][nt][1] + tA.y);
                *(float2*)&sOut[rB * OPAD + c0] =
                    make_float2(acc[mt][nt][2] + tB.x, acc[mt][nt][3] + tB.y);
            }
        }
        __syncthreads();

        // ---- coalesced store + register stats ----
        #pragma unroll
        for (int i = 0; i < 8; i++) {
            int row = i * 16 + wrow;            // idx = i*512+tid; c4 = lane
            float4 v = *(float4*)&sOut[row * OPAD + cbase];
            *(float4*)&g_fused[(size_t)(brow + row) * 128 + cbase] = v;
            sacc[0] += v.x; qacc[0] += v.x * v.x;
            sacc[1] += v.y; qacc[1] += v.y * v.y;
            sacc[2] += v.z; qacc[2] += v.z * v.z;
            sacc[3] += v.w; qacc[3] += v.w * v.w;
        }
    }

    // ---- final: stats -> smem -> g_partial ----
    #pragma unroll
    for (int j = 0; j < 4; j++) {
        bufS[(cbase + j) * 16 + wrow] = sacc[j];
        bufQ[(cbase + j) * 16 + wrow] = qacc[j];
    }
    __syncthreads();
    if (tid < 128) {
        float s = 0.f, q = 0.f;
        #pragma unroll
        for (int i = 0; i < 16; i++) { s += bufS[tid * 16 + i]; q += bufQ[tid * 16 + i]; }
        g_partial[tid * NSM + bid]   = s;
        g_partialsq[tid * NSM + bid] = q;
    }
}

// =====================================================================
// stats: reduce 148 partials -> BN scale/shift (deterministic)
// =====================================================================
__global__ void stats_kernel(const float* __restrict__ gamma,
                             const float* __restrict__ beta) {
    const int c = blockIdx.x;
    const int tid = threadIdx.x;
    __shared__ float rs[256], rq[256];
    float s = 0.f, q = 0.f;
    if (tid < NSM) {
        s = g_partial[c * NSM + tid];
        q = g_partialsq[c * NSM + tid];
    }
    rs[tid] = s; rq[tid] = q;
    __syncthreads();
    for (int o = 128; o > 0; o >>= 1) {
        if (tid < o) { rs[tid] += rs[tid + o]; rq[tid] += rq[tid + o]; }
        __syncthreads();
    }
    if (tid == 0) {
        float mu  = rs[0] / (float)N_PTS;
        float var = rq[0] / (float)N_PTS - mu * mu;
        float sc  = gamma[c] * rsqrtf(var + 1e-5f);
        g_scale[c] = sc;
        g_shift[c] = beta[c] - mu * sc;
    }
}

// =====================================================================
// head2: preds = heads(relu(BN(fused))); finalize folded in.
// g_fused rows are staged chunk-wise through smem so global loads are
// coalesced (thread-per-point direct reads would be 32 lines/instr).
// =====================================================================
#define HSTR 36    // stage row stride in floats (16B-aligned, conflict-free)
__global__ void __launch_bounds__(256)
head2_kernel(const int* __restrict__ labels,
             const float* __restrict__ Wb, const float* __restrict__ bb,
             const float* __restrict__ Wc, const float* __restrict__ bc,
             float* __restrict__ out) {
    __shared__ float4 sw[9][32];
    __shared__ float4 ssc[32], ssh[32];
    __shared__ float sb[9];
    __shared__ float skth[NG];
    __shared__ int   slab[NG];
    __shared__ __align__(16) float stage[256 * HSTR];   // 36 KB
    const int tid = threadIdx.x;
    for (int i = tid; i < 288; i += 256) {
        int j = i >> 5, k4 = i & 31, k = k4 * 4;
        float4 w;
        if (j < 7) w = make_float4(Wb[(k+0)*7+j], Wb[(k+1)*7+j], Wb[(k+2)*7+j], Wb[(k+3)*7+j]);
        else { int jc = j - 7;
               w = make_float4(Wc[(k+0)*2+jc], Wc[(k+1)*2+jc], Wc[(k+2)*2+jc], Wc[(k+3)*2+jc]); }
        sw[j][k4] = w;
    }
    if (tid < 32) { ssc[tid] = ((const float4*)g_scale)[tid]; ssh[tid] = ((const float4*)g_shift)[tid]; }
    if (tid < 9) sb[tid] = (tid < 7) ? bb[tid] : bc[tid - 7];
    if (tid < NG) { skth[tid] = g_kth[tid]; slab[tid] = labels[tid]; }
    __syncthreads();

    const int pbase = blockIdx.x * 256;
    const int p = pbase + tid;
    float acc[9];
    #pragma unroll
    for (int j = 0; j < 9; j++) acc[j] = sb[j];
    const float4* gf = (const float4*)g_fused;

    #pragma unroll 1
    for (int ch = 0; ch < 4; ch++) {            // 32-channel chunks
        // coalesced load: 256 rows x 8 float4 of this chunk
        #pragma unroll
        for (int i = 0; i < 8; i++) {
            int idx = i * 256 + tid;
            int row = idx >> 3, f4 = idx & 7;
            float4 v = gf[(size_t)(pbase + row) * 32 + ch * 8 + f4];
            *(float4*)&stage[row * HSTR + f4 * 4] = v;
        }
        __syncthreads();
        #pragma unroll
        for (int kl = 0; kl < 8; kl++) {
            const int k4 = ch * 8 + kl;
            float4 f = *(float4*)&stage[tid * HSTR + kl * 4];
            float4 sc = ssc[k4], sh = ssh[k4];
            float x0 = fmaxf(fmaf(f.x, sc.x, sh.x), 0.f);
            float x1 = fmaxf(fmaf(f.y, sc.y, sh.y), 0.f);
            float x2 = fmaxf(fmaf(f.z, sc.z, sh.z), 0.f);
            float x3 = fmaxf(fmaf(f.w, sc.w, sh.w), 0.f);
            #pragma unroll
            for (int j = 0; j < 9; j++) {
                float4 w = sw[j][k4];
                acc[j] = fmaf(x0, w.x, acc[j]);
                acc[j] = fmaf(x1, w.y, acc[j]);
                acc[j] = fmaf(x2, w.z, acc[j]);
                acc[j] = fmaf(x3, w.w, acc[j]);
            }
        }
        __syncthreads();
    }
    float* o = out + (size_t)p * 9;
    o[0] = acc[0]; o[1] = acc[1]; o[2] = acc[2];
    o[3] = expf(acc[3]); o[4] = expf(acc[4]); o[5] = expf(acc[5]);
    o[6] = acc[6]; o[7] = acc[7]; o[8] = acc[8];

    const int lvl = (p < NL0) ? 0 : 1;
    const int bi = g_bi[p];
    const float d2 = g_bd[p];
    int a = (slab[bi] == lvl && d2 < skth[bi]) ? bi : -1;
    out[(size_t)N_PTS * 9 + p] = (float)a;
}

// =====================================================================
// cand: candidates within radius + per-point global argmin (bi, d2).
// =====================================================================
__global__ void __launch_bounds__(256)
cand_kernel(const float* __restrict__ p0, const float* __restrict__ p1,
            const float* __restrict__ boxes, const int* __restrict__ labels) {
    __shared__ float4 sc0[NG], sc1[NG];
    const int tid = threadIdx.x;
    if (tid < NG) {
        float cx = boxes[tid * 7 + 0], cy = boxes[tid * 7 + 1], cz = boxes[tid * 7 + 2];
        int lvl = labels[tid];
        sc0[tid] = make_float4(cx, cy, cz, (lvl == 0) ? R2_L0 : -1.0f);
        sc1[tid] = make_float4(cx, cy, cz, (lvl == 1) ? R2_L1 : -1.0f);
    }
    __syncthreads();

    const int p = blockIdx.x * 256 + tid;
    float px, py, pz; const float4* Cc;
    if (p < NL0) { px = p0[3 * p]; py = p0[3 * p + 1]; pz = p0[3 * p + 2]; Cc = sc0; }
    else { int q = p - NL0; px = p1[3 * q]; py = p1[3 * q + 1]; pz = p1[3 * q + 2]; Cc = sc1; }

    float bestA = 3.4e38f; int biA = 0;
    float bestB = 3.4e38f; int biB = 64;
    #pragma unroll 4
    for (int g = 0; g < 64; g++) {
        float4 cA = Cc[g];
        float dxA = px - cA.x, dyA = py - cA.y, dzA = pz - cA.z;
        float dA = fmaf(dzA, dzA, fmaf(dyA, dyA, dxA * dxA));
        if (dA < bestA) { bestA = dA; biA = g; }
        if (dA < cA.w) {
            int idx = atomicAdd(&g_cnt[g], 1);
            if (idx < CAND_CAP) g_cand[(size_t)g * CAND_CAP + idx] = dA;
        }
        float4 cB = Cc[g + 64];
        float dxB = px - cB.x, dyB = py - cB.y, dzB = pz - cB.z;
        float dB = fmaf(dzB, dzB, fmaf(dyB, dyB, dxB * dxB));
        if (dB < bestB) { bestB = dB; biB = g + 64; }
        if (dB < cB.w) {
            int idx = atomicAdd(&g_cnt[g + 64], 1);
            if (idx < CAND_CAP) g_cand[(size_t)(g + 64) * CAND_CAP + idx] = dB;
        }
    }
    int bi = (bestB < bestA) ? biB : biA;
    float best = (bestB < bestA) ? bestB : bestA;
    g_bi[p] = bi;
    g_bd[p] = best;
}

// =====================================================================
// select: exact 33rd-smallest per gt (candidates; full-scan fallback)
// =====================================================================
#define NBUCK 4096
#define BSCALE 235.0f
#define BCANDMAX 2048
#define KSEL 33

__global__ void __launch_bounds__(512)
select_kernel(const float* __restrict__ p0, const float* __restrict__ p1,
              const float* __restrict__ boxes, const int* __restrict__ labels) {
    const int g = blockIdx.x;
    const int tid = threadIdx.x;
    __shared__ unsigned hist[NBUCK];
    __shared__ unsigned csum[512];
    __shared__ float bcand[BCANDMAX];
    __shared__ int sInfo[3];

    const int lvl = labels[g];
    const float* pts = lvl ? p1 : p0;
    const int n = lvl ? NL1 : NL0;
    const float cx = boxes[g * 7 + 0], cy = boxes[g * 7 + 1], cz = boxes[g * 7 + 2];

    const int cnt = g_cnt[g];
    const bool ok = (cnt >= KSEL && cnt <= CAND_CAP);
    const float* src = &g_cand[(size_t)g * CAND_CAP];
    const int m = ok ? cnt : n;

    for (int i = tid; i < NBUCK; i += 512) hist[i] = 0u;
    if (tid == 0) sInfo[2] = 0;
    __syncthreads();

    for (int i = tid; i < m; i += 512) {
        float d2;
        if (ok) d2 = src[i];
        else {
            float dx = pts[3 * i] - cx, dy = pts[3 * i + 1] - cy, dz = pts[3 * i + 2] - cz;
            d2 = fmaf(dz, dz, fmaf(dy, dy, dx * dx));
        }
        int b = (int)(sqrtf(d2) * BSCALE); b = b > (NBUCK - 1) ? (NBUCK - 1) : b;
        atomicAdd(&hist[b], 1u);
    }
    __syncthreads();

    unsigned cs = 0;
    #pragma unroll
    for (int i = 0; i < 8; i++) cs += hist[tid * 8 + i];
    csum[tid] = cs;
    __syncthreads();
    if (tid == 0) {
        unsigned run = 0; int chunk = 0;
        while (chunk < 512 && run + csum[chunk] < KSEL) { run += csum[chunk]; chunk++; }
        int B = chunk * 8;
        while (run + hist[B] < KSEL) { run += hist[B]; B++; }
        sInfo[0] = B; sInfo[1] = (int)run;
    }
    __syncthreads();
    const int B = sInfo[0];

    for (int i = tid; i < m; i += 512) {
        float d2;
        if (ok) d2 = src[i];
        else {
            float dx = pts[3 * i] - cx, dy = pts[3 * i + 1] - cy, dz = pts[3 * i + 2] - cz;
            d2 = fmaf(dz, dz, fmaf(dy, dy, dx * dx));
        }
        int b = (int)(sqrtf(d2) * BSCALE); b = b > (NBUCK - 1) ? (NBUCK - 1) : b;
        if (b == B) {
            int pos = atomicAdd(&sInfo[2], 1);
            if (pos < BCANDMAX) bcand[pos] = d2;
        }
    }
    __syncthreads();
    if (tid == 0) {
        int mb = sInfo[2]; if (mb > BCANDMAX) mb = BCANDMAX;
        int need = KSEL - sInfo[1];
        float kth = 1e8f;
        for (int r = 0; r < need; r++) {
            float best = 3.4e38f; int bi = 0;
            for (int i = 0; i < mb; i++) { float v = bcand[i]; if (v < best) { best = v; bi = i; } }
            kth = best; bcand[bi] = 3.4e38f;
        }
        g_kth[g] = kth;
    }
}

// =====================================================================
// launch — gemm kept 4th so ncu profiles it
// =====================================================================
extern "C" void kernel_launch(void* const* d_in, const int* in_sizes, int n_in,
                              void* d_out, int out_size) {
    const float* bf    = (const float*)d_in[0];
    const float* text  = (const float*)d_in[1];
    const float* Wf    = (const float*)d_in[2];
    const float* bfu   = (const float*)d_in[3];
    const float* gamma = (const float*)d_in[4];
    const float* beta  = (const float*)d_in[5];
    const float* Wb    = (const float*)d_in[6];
    const float* bb    = (const float*)d_in[7];
    const float* Wc    = (const float*)d_in[8];
    const float* bc    = (const float*)d_in[9];
    const float* p0    = (const float*)d_in[10];
    const float* p1    = (const float*)d_in[11];
    const bool sig = (in_sizes[12] == 128 * 7);
    const float* boxes  = (const float*)d_in[sig ? 12 : 14];
    const int*   bidx   = (const int*)  d_in[sig ? 13 : 12];
    const int*   labels = (const int*)  d_in[sig ? 14 : 13];
    float* out = (float*)d_out;

    cudaFuncSetAttribute(gemm_kernel, cudaFuncAttributeMaxDynamicSharedMemorySize,
                         GEMM_SMEM);

    prep_kernel<<<65, 256>>>(Wf, text, bfu);                        // 1
    cand_kernel<<<N_PTS / 256, 256>>>(p0, p1, boxes, labels);       // 2
    select_kernel<<<NG, 512>>>(p0, p1, boxes, labels);              // 3
    gemm_kernel<<<NSM, 512, GEMM_SMEM>>>(bf, bidx);                 // 4 <- profiled
    stats_kernel<<<128, 256>>>(gamma, beta);                        // 5
    head2_kernel<<<N_PTS / 256, 256>>>(labels, Wb, bb, Wc, bc, out);// 6
}